// round 10
// baseline (speedup 1.0000x reference)
#include <cuda_runtime.h>
#include <cuda_bf16.h>

// ---------------- problem constants ----------------
#define B_SZ     2
#define L_SEQ    1024
#define D_MODEL  1024
#define D_INNER  4096
#define N_STATE  16
#define DT_RANK  64
#define M_ROWS   (B_SZ * L_SEQ)          // 2048
#define XDBL_LD  128                     // padded x_dbl leading dim

// ---------------- scratch (device globals; no allocs allowed) ----------------
__device__ float g_xz   [(long)M_ROWS * 2 * D_INNER]; // 2048 x 8192  (xc | res)
__device__ float g_xdbl [(long)M_ROWS * XDBL_LD];     // 2048 x 128 (cols 96..127 pad)
__device__ float g_delta[(long)M_ROWS * D_INNER];     // 2048 x 4096
__device__ float g_partx[8L * M_ROWS * XDBL_LD];      // split-K partials (xdbl)
__device__ float g_party[4L * M_ROWS * D_MODEL];      // split-K partials (out)
__device__ __nv_bfloat16 g_ap [(long)M_ROWS * 3 * D_INNER];  // u'/y' split
__device__ __nv_bfloat16 g_ap2[(long)M_ROWS * 3 * DT_RANK];  // delta-GEMM A'
__device__ __nv_bfloat16 g_wp [(long)(2 * D_INNER) * 3 * D_MODEL];

// ---------------- helpers ----------------
__device__ __forceinline__ float siluf(float x) { return x / (1.0f + __expf(-x)); }
__device__ __forceinline__ float softplusf(float x) {
    return (x > 0.0f) ? (x + log1pf(expf(-x))) : log1pf(expf(x));
}
__device__ __forceinline__ unsigned smem_u32(const void* p) {
    unsigned a;
    asm("{ .reg .u64 t; cvta.to.shared.u64 t, %1; cvt.u32.u64 %0, t; }" : "=r"(a) : "l"(p));
    return a;
}
#define SWZ128(o) ((o) ^ (((o) >> 3) & 0x70))

__device__ __forceinline__ void ldsm4(unsigned* r, unsigned addr) {
    asm volatile("ldmatrix.sync.aligned.m8n8.x4.shared.b16 {%0,%1,%2,%3}, [%4];"
                 : "=r"(r[0]), "=r"(r[1]), "=r"(r[2]), "=r"(r[3]) : "r"(addr));
}
__device__ __forceinline__ void mma16816(float* c, const unsigned* a, const unsigned* b) {
    asm volatile("mma.sync.aligned.m16n8k16.row.col.f32.bf16.bf16.f32 "
                 "{%0,%1,%2,%3}, {%4,%5,%6,%7}, {%8,%9}, {%0,%1,%2,%3};"
                 : "+f"(c[0]), "+f"(c[1]), "+f"(c[2]), "+f"(c[3])
                 : "r"(a[0]), "r"(a[1]), "r"(a[2]), "r"(a[3]), "r"(b[0]), "r"(b[1]));
}
#define CP_ASYNC16(dst, src) \
    asm volatile("cp.async.cg.shared.global [%0], [%1], 16;" :: "r"(dst), "l"(src) : "memory")
#define CP_COMMIT() asm volatile("cp.async.commit_group;" ::: "memory")
#define CP_WAIT(n)  asm volatile("cp.async.wait_group %0;" :: "n"(n) : "memory")

__device__ __forceinline__ void split_store(__nv_bfloat16* base, long o, long K, float v) {
    __nv_bfloat16 hb = __float2bfloat16(v);
    float h = __bfloat162float(hb);
    __nv_bfloat16 lb = __float2bfloat16(v - h);
    base[o]         = hb;
    base[o + K]     = lb;
    base[o + 2 * K] = hb;
}

// ---------------- split prep kernels ----------------
__global__ __launch_bounds__(256)
void prep_act(const float* __restrict__ A, int lda, int K,
              __nv_bfloat16* __restrict__ Ap)
{
    long idx = (long)blockIdx.x * 256 + threadIdx.x;
    long m = idx / K;
    int  k = (int)(idx % K);
    split_store(Ap, m * (3L * K) + k, K, A[m * lda + k]);
}

__global__ __launch_bounds__(256)
void prep_w(const float* __restrict__ W, int N, int K,
            __nv_bfloat16* __restrict__ Wp)
{
    __shared__ float th[32][33];
    __shared__ float tl[32][33];
    int bk = blockIdx.x * 32, bn = blockIdx.y * 32;
    int tx = threadIdx.x & 31, ty = threadIdx.x >> 5;
#pragma unroll
    for (int j = 0; j < 4; j++) {
        int k = bk + ty + j * 8;
        float w = W[(long)k * N + bn + tx];
        float h = __bfloat162float(__float2bfloat16(w));
        th[ty + j * 8][tx] = h;
        tl[ty + j * 8][tx] = w - h;
    }
    __syncthreads();
#pragma unroll
    for (int j = 0; j < 4; j++) {
        int n = bn + ty + j * 8;
        long o = (long)n * (3L * K);
        __nv_bfloat16 hb = __float2bfloat16(th[tx][ty + j * 8]);
        __nv_bfloat16 lb = __float2bfloat16(tl[tx][ty + j * 8]);
        Wp[o + bk + tx]         = hb;
        Wp[o + K + bk + tx]     = hb;
        Wp[o + 2 * K + bk + tx] = lb;
    }
}

__global__ __launch_bounds__(256)
void zero_wp_pad(__nv_bfloat16* __restrict__ Wp)
{
    long i = (long)blockIdx.x * 256 + threadIdx.x;
    Wp[96L * 12288 + i] = __float2bfloat16(0.0f);
}

__global__ __launch_bounds__(256)
void reduce_parts(const float* __restrict__ parts, float* __restrict__ dst,
                  long n, int np)
{
    long i = ((long)blockIdx.x * 256 + threadIdx.x) * 4;
    if (i >= n) return;
    float4 s = *reinterpret_cast<const float4*>(parts + i);
    for (int p = 1; p < np; p++) {
        float4 v = *reinterpret_cast<const float4*>(parts + (long)p * n + i);
        s.x += v.x; s.y += v.y; s.z += v.z; s.w += v.w;
    }
    *reinterpret_cast<float4*>(dst + i) = s;
}

// ---------------- warp-MMA bf16 GEMM: C[M,N] = A'[M,K'] @ W'[N,K']^T -------
// BM=128, BN=128, BK=64 bf16 (128B rows, SW128), 3-stage cp.async ring,
// one __syncthreads per K-tile, 2 CTAs/SM. 8 warps of 32x64.
// Grid-swizzled rasterization (G=8 N-tiles/stripe) for L2 reuse.
// blockIdx.z = split-K slice (T tiles each). EPI: 0=none, 1=softplus.
#define STAGES 3
#define STG    32768u
#define GSMEM_TOTAL (STAGES * 32768)

template<int EPI>
__global__ __launch_bounds__(256, 2)
void gemm_mma(const __nv_bfloat16* __restrict__ Ap, int lda,
              const __nv_bfloat16* __restrict__ Bp, int ldb,
              float* __restrict__ C, int ldc, int T, long csplit)
{
    extern __shared__ __align__(1024) char smem[];
    const unsigned sb = smem_u32(smem);
    const int tid  = threadIdx.x;
    const int lane = tid & 31;
    const int wid  = tid >> 5;
    const int wm   = (wid & 3) * 32;
    const int wn   = (wid >> 2) * 64;

    // ---- grid swizzle: stripe of G n-tiles x all m-tiles ----
    const int gridN = gridDim.x, gridM = gridDim.y;
    const int G = (gridN < 8) ? gridN : 8;           // gridN in {1,8,32,64}
    const int bid = blockIdx.y * gridN + blockIdx.x;
    const int stripe = G * gridM;
    const int bn_i = (bid / stripe) * G + (bid % stripe) % G;
    const int bm_i = (bid % stripe) / G;
    const long bm = (long)bm_i * 128;
    const long bn = (long)bn_i * 128;

    Ap += (long)blockIdx.z * T * 64;
    Bp += (long)blockIdx.z * T * 64;
    C  += (long)blockIdx.z * csplit;

    const int ldr  = tid >> 3;
    const int ldc8 = (tid & 7) * 8;

    float acc[2][8][4];
#pragma unroll
    for (int i = 0; i < 2; i++)
#pragma unroll
        for (int j = 0; j < 8; j++)
#pragma unroll
            for (int r = 0; r < 4; r++) acc[i][j][r] = 0.0f;

    auto load_tile = [&](int t, int s) {
        const __nv_bfloat16* Ab = Ap + bm * lda + (long)t * 64;
        const __nv_bfloat16* Bb = Bp + bn * ldb + (long)t * 64;
        unsigned oa = sb + (unsigned)s * STG;
        unsigned ob = oa + 16384u;
#pragma unroll
        for (int i = 0; i < 4; i++) {
            int r = ldr + 32 * i;
            unsigned sw = SWZ128((unsigned)(r * 128 + ldc8 * 2));
            CP_ASYNC16(oa + sw, Ab + (long)r * lda + ldc8);
            CP_ASYNC16(ob + sw, Bb + (long)r * ldb + ldc8);
        }
        CP_COMMIT();
    };

#pragma unroll
    for (int s = 0; s < STAGES - 1; s++) {
        if (s < T) load_tile(s, s);
        else       CP_COMMIT();
    }

    const int lr = lane & 15;
    const int lh = (lane >> 4) * 16;

    int stage = 0;
    for (int t = 0; t < T; t++) {
        CP_WAIT(STAGES - 2);
        __syncthreads();
        {
            int tn = t + STAGES - 1;
            int sn = stage + STAGES - 1; if (sn >= STAGES) sn -= STAGES;
            if (tn < T) load_tile(tn, sn);
            else        CP_COMMIT();
        }
        const unsigned sA = sb + (unsigned)stage * STG;
        const unsigned sB = sA + 16384u;
#pragma unroll
        for (int ks = 0; ks < 4; ks++) {
            const int kb = ks * 32;
            unsigned af[2][4];
#pragma unroll
            for (int im = 0; im < 2; im++) {
                unsigned addr = sA + SWZ128((unsigned)((wm + im * 16 + lr) * 128 + kb + lh));
                ldsm4(af[im], addr);
            }
            unsigned bf[8][2];
#pragma unroll
            for (int jn = 0; jn < 4; jn++) {
                unsigned q[4];
                unsigned addr = sB + SWZ128((unsigned)((wn + jn * 16 + lr) * 128 + kb + lh));
                ldsm4(q, addr);
                bf[2 * jn][0]     = q[0];
                bf[2 * jn][1]     = q[2];
                bf[2 * jn + 1][0] = q[1];
                bf[2 * jn + 1][1] = q[3];
            }
#pragma unroll
            for (int im = 0; im < 2; im++)
#pragma unroll
                for (int j = 0; j < 8; j++)
                    mma16816(acc[im][j], af[im], bf[j]);
        }
        if (++stage == STAGES) stage = 0;
    }

    const int gid = lane >> 2;
    const int tig = lane & 3;
#pragma unroll
    for (int im = 0; im < 2; im++) {
        long m0 = bm + wm + im * 16 + gid;
#pragma unroll
        for (int j = 0; j < 8; j++) {
            long n0 = bn + wn + j * 8 + 2 * tig;
            float c0 = acc[im][j][0], c1 = acc[im][j][1];
            float c2 = acc[im][j][2], c3 = acc[im][j][3];
            if (EPI == 1) {
                c0 = softplusf(c0); c1 = softplusf(c1);
                c2 = softplusf(c2); c3 = softplusf(c3);
            }
            *reinterpret_cast<float2*>(C + m0 * ldc + n0)       = make_float2(c0, c1);
            *reinterpret_cast<float2*>(C + (m0 + 8) * ldc + n0) = make_float2(c2, c3);
        }
    }
}

// ---------------- depthwise causal conv(4) + bias + SiLU + u-split ---------
// Each thread computes 4 consecutive t for one d. u stored ONLY as split
// (scan reconstructs u = uh + ul from g_ap).
__global__ __launch_bounds__(256)
void conv_silu_kernel(const float* __restrict__ Wconv,
                      const float* __restrict__ bconv)
{
    long idx = (long)blockIdx.x * 256 + threadIdx.x;   // over B * L/4 * D
    int d  = (int)(idx & (D_INNER - 1));
    int t4 = (int)((idx >> 12) & (L_SEQ / 4 - 1));
    int b  = (int)(idx >> 20);
    int t0 = t4 * 4;

    float w0 = Wconv[d * 4 + 0], w1 = Wconv[d * 4 + 1];
    float w2 = Wconv[d * 4 + 2], w3 = Wconv[d * 4 + 3];
    float bc = bconv[d];

    const long rowbase = (long)(b * L_SEQ) * (2 * D_INNER) + d;
    float v[7];
#pragma unroll
    for (int i = 0; i < 7; i++) {
        int tt = t0 - 3 + i;
        v[i] = (tt >= 0) ? g_xz[rowbase + (long)tt * (2 * D_INNER)] : 0.0f;
    }

    long m = (long)(b * L_SEQ + t0);
#pragma unroll
    for (int q = 0; q < 4; q++) {
        float acc = bc;
        acc = fmaf(v[q],     w0, acc);
        acc = fmaf(v[q + 1], w1, acc);
        acc = fmaf(v[q + 2], w2, acc);
        acc = fmaf(v[q + 3], w3, acc);
        split_store(g_ap, (m + q) * (3L * D_INNER) + d, D_INNER, siluf(acc));
    }
}

// ---------------- selective scan + epilogue + y-split ----------------------
// u reconstructed from g_ap split; da powers via log-depth squaring tree.
__global__ __launch_bounds__(128)
void scan_kernel(const float* __restrict__ A_log,
                 const float* __restrict__ Dp)
{
    extern __shared__ __align__(16) float sBC[];   // [L_SEQ][32]
    const int b = blockIdx.x >> 5;
    const int d = ((blockIdx.x & 31) << 7) + threadIdx.x;
    const long base = (long)b * L_SEQ;

    for (int i = threadIdx.x * 4; i < L_SEQ * 32; i += 128 * 4) {
        int t = i >> 5, c = i & 31;
        *reinterpret_cast<float4*>(&sBC[i]) =
            *reinterpret_cast<const float4*>(&g_xdbl[(base + t) * XDBL_LD + DT_RANK + c]);
    }
    __syncthreads();

    float A[N_STATE];
#pragma unroll
    for (int n = 0; n < N_STATE; n++)
        A[n] = -__expf(A_log[d * N_STATE + n]);
    const float A1 = A[0];
    bool fast = true;
#pragma unroll
    for (int n = 1; n < N_STATE; n++)
        fast = fast && (fabsf(A[n] - (float)(n + 1) * A1) <= 1e-4f * fabsf(A[n]) + 1e-30f);

    const float Dd = Dp[d];
    float h[N_STATE];
#pragma unroll
    for (int n = 0; n < N_STATE; n++) h[n] = 0.0f;

    // software-pipelined loads (depth 4): delta fp32; u from split; res fp32
    float pdt[4], pu[4], pr[4];
    auto load_q = [&](int t, int q) {
        long row = base + t;
        pdt[q] = g_delta[row * D_INNER + d];
        long o = row * (3L * D_INNER) + d;
        pu[q] = __bfloat162float(g_ap[o]) + __bfloat162float(g_ap[o + D_INNER]);
        pr[q] = g_xz[row * (2 * D_INNER) + D_INNER + d];
    };
#pragma unroll
    for (int q = 0; q < 4; q++) load_q(q, q);

    for (int t0 = 0; t0 < L_SEQ; t0 += 4) {
        float cdt[4], cu[4], cr[4];
#pragma unroll
        for (int q = 0; q < 4; q++) { cdt[q] = pdt[q]; cu[q] = pu[q]; cr[q] = pr[q]; }
        if (t0 + 4 < L_SEQ) {
#pragma unroll
            for (int q = 0; q < 4; q++) load_q(t0 + 4 + q, q);
        }
#pragma unroll
        for (int q = 0; q < 4; q++) {
            const int t = t0 + q;
            const float* BC = &sBC[t * 32];
            const float dt = cdt[q], uu = cu[q], rr = cr[q];
            const float dtu = dt * uu;
            float yv = 0.0f;
            if (fast) {
                // pw[n] = p^(n+1) via squaring tree (depth ~4)
                const float p1 = __expf(dt * A1);
                const float p2 = p1 * p1;
                const float p4 = p2 * p2;
                const float p8 = p4 * p4;
                float pw[N_STATE];
                pw[0] = p1;        pw[1] = p2;        pw[2] = p2 * p1;   pw[3] = p4;
                pw[4] = p4 * p1;   pw[5] = p4 * p2;   pw[6] = p4 * pw[2];pw[7] = p8;
                pw[8] = p8 * p1;   pw[9] = p8 * p2;   pw[10] = p8 * pw[2]; pw[11] = p8 * p4;
                pw[12] = p8 * pw[4]; pw[13] = p8 * pw[5]; pw[14] = p8 * pw[6]; pw[15] = p8 * p8;
#pragma unroll
                for (int n = 0; n < N_STATE; n++) {
                    h[n] = fmaf(pw[n], h[n], dtu * BC[n]);
                    yv = fmaf(h[n], BC[N_STATE + n], yv);
                }
            } else {
#pragma unroll
                for (int n = 0; n < N_STATE; n++) {
                    float da = __expf(dt * A[n]);
                    h[n] = fmaf(da, h[n], dtu * BC[n]);
                    yv = fmaf(h[n], BC[N_STATE + n], yv);
                }
            }
            float yo = (yv + uu * Dd) * siluf(rr);
            split_store(g_ap, (base + t) * (3L * D_INNER) + d, D_INNER, yo);
        }
    }
}

// ---------------- launcher ----------------
extern "C" void kernel_launch(void* const* d_in, const int* in_sizes, int n_in,
                              void* d_out, int out_size)
{
    (void)in_sizes; (void)n_in; (void)out_size;
    const float* x     = (const float*)d_in[0];
    const float* Win   = (const float*)d_in[1];
    const float* Wconv = (const float*)d_in[2];
    const float* bconv = (const float*)d_in[3];
    const float* Wx    = (const float*)d_in[4];
    const float* Wdt   = (const float*)d_in[5];
    const float* A_log = (const float*)d_in[6];
    const float* D     = (const float*)d_in[7];
    const float* Wout  = (const float*)d_in[8];
    float* out = (float*)d_out;

    float *xz, *xdbl, *delta, *partx, *party;
    __nv_bfloat16 *ap, *ap2, *wp;
    cudaGetSymbolAddress((void**)&xz,    g_xz);
    cudaGetSymbolAddress((void**)&xdbl,  g_xdbl);
    cudaGetSymbolAddress((void**)&delta, g_delta);
    cudaGetSymbolAddress((void**)&partx, g_partx);
    cudaGetSymbolAddress((void**)&party, g_party);
    cudaGetSymbolAddress((void**)&ap,    g_ap);
    cudaGetSymbolAddress((void**)&ap2,   g_ap2);
    cudaGetSymbolAddress((void**)&wp,    g_wp);

    cudaFuncSetAttribute(gemm_mma<0>, cudaFuncAttributeMaxDynamicSharedMemorySize, GSMEM_TOTAL);
    cudaFuncSetAttribute(gemm_mma<1>, cudaFuncAttributeMaxDynamicSharedMemorySize, GSMEM_TOTAL);
    const int scan_smem = L_SEQ * 32 * sizeof(float);
    cudaFuncSetAttribute(scan_kernel, cudaFuncAttributeMaxDynamicSharedMemorySize, scan_smem);

    // ---- GEMM1: xz = x @ Win   (2048 x 8192, K'=3072, T=48) ----
    prep_w<<<dim3(D_MODEL / 32, 2 * D_INNER / 32), 256>>>(Win, 2 * D_INNER, D_MODEL, wp);
    prep_act<<<(M_ROWS * D_MODEL) / 256, 256>>>(x, D_MODEL, D_MODEL, ap);
    gemm_mma<0><<<dim3(2 * D_INNER / 128, M_ROWS / 128, 1), 256, GSMEM_TOTAL>>>(
        ap, 3 * D_MODEL, wp, 3 * D_MODEL, xz, 2 * D_INNER, 48, 0);

    // ---- conv + SiLU -> u' (split, into ap) ----
    conv_silu_kernel<<<(B_SZ * (L_SEQ / 4) * D_INNER) / 256, 256>>>(Wconv, bconv);

    // ---- x_dbl = u @ Wx   (2048 x 128pad, K'=12288; split-K x8, T=24) ----
    prep_w<<<dim3(D_INNER / 32, 96 / 32), 256>>>(Wx, 96, D_INNER, wp);
    zero_wp_pad<<<(32 * 12288) / 256, 256>>>(wp);
    gemm_mma<0><<<dim3(1, M_ROWS / 128, 8), 256, GSMEM_TOTAL>>>(
        ap, 3 * D_INNER, wp, 3 * D_INNER, partx, XDBL_LD, 24, (long)M_ROWS * XDBL_LD);
    reduce_parts<<<(M_ROWS * XDBL_LD) / 1024, 256>>>(partx, xdbl, (long)M_ROWS * XDBL_LD, 8);

    // ---- delta = softplus(x_dbl[:, :64] @ Wdt)  (2048 x 4096, K'=192, T=3) ----
    prep_w<<<dim3(DT_RANK / 32, D_INNER / 32), 256>>>(Wdt, D_INNER, DT_RANK, wp);
    prep_act<<<(M_ROWS * DT_RANK) / 256, 256>>>(xdbl, XDBL_LD, DT_RANK, ap2);
    gemm_mma<1><<<dim3(D_INNER / 128, M_ROWS / 128, 1), 256, GSMEM_TOTAL>>>(
        ap2, 3 * DT_RANK, wp, 3 * DT_RANK, delta, D_INNER, 3, 0);

    // ---- selective scan + epilogue -> y' (split, into ap) ----
    prep_w<<<dim3(D_INNER / 32, D_MODEL / 32), 256>>>(Wout, D_MODEL, D_INNER, wp);
    scan_kernel<<<64, 128, scan_smem>>>(A_log, D);

    // ---- out = y @ Wout   (2048 x 1024, K'=12288; split-K x4, T=48) ----
    gemm_mma<0><<<dim3(D_MODEL / 128, M_ROWS / 128, 4), 256, GSMEM_TOTAL>>>(
        ap, 3 * D_INNER, wp, 3 * D_INNER, party, D_MODEL, 48, (long)M_ROWS * D_MODEL);
    reduce_parts<<<(M_ROWS * D_MODEL) / 1024, 256>>>(party, out, (long)M_ROWS * D_MODEL, 4);
}

// round 11
// speedup vs baseline: 1.0005x; 1.0005x over previous
#include <cuda_runtime.h>
#include <cuda_bf16.h>

// ---------------- problem constants ----------------
#define B_SZ     2
#define L_SEQ    1024
#define D_MODEL  1024
#define D_INNER  4096
#define N_STATE  16
#define DT_RANK  64
#define M_ROWS   (B_SZ * L_SEQ)          // 2048
#define XDBL_LD  128                     // padded x_dbl leading dim

// ---------------- scratch (device globals; no allocs allowed) ----------------
__device__ float g_xz   [(long)M_ROWS * 2 * D_INNER]; // 2048 x 8192  (xc | res)
__device__ float g_u    [(long)M_ROWS * D_INNER];     // 2048 x 4096 (fp32 for scan)
__device__ float g_xdbl [(long)M_ROWS * XDBL_LD];     // 2048 x 128 (cols 96..127 pad)
__device__ float g_delta[(long)M_ROWS * D_INNER];     // 2048 x 4096
__device__ float g_partx[16L * M_ROWS * XDBL_LD];     // split-K partials (xdbl)
__device__ float g_party[2L * M_ROWS * D_MODEL];      // split-K partials (out)
__device__ __nv_bfloat16 g_ap [(long)M_ROWS * 3 * D_INNER];  // u'/y' split
__device__ __nv_bfloat16 g_ap2[(long)M_ROWS * 3 * DT_RANK];  // delta-GEMM A'
__device__ __nv_bfloat16 g_wp [(long)(2 * D_INNER) * 3 * D_MODEL];

// ---------------- helpers ----------------
__device__ __forceinline__ float siluf(float x) { return x / (1.0f + __expf(-x)); }
__device__ __forceinline__ float softplusf(float x) {
    return (x > 0.0f) ? (x + log1pf(expf(-x))) : log1pf(expf(x));
}
__device__ __forceinline__ unsigned smem_u32(const void* p) {
    unsigned a;
    asm("{ .reg .u64 t; cvta.to.shared.u64 t, %1; cvt.u32.u64 %0, t; }" : "=r"(a) : "l"(p));
    return a;
}
#define SWZ128(o) ((o) ^ (((o) >> 3) & 0x70))

__device__ __forceinline__ void ldsm4(unsigned* r, unsigned addr) {
    asm volatile("ldmatrix.sync.aligned.m8n8.x4.shared.b16 {%0,%1,%2,%3}, [%4];"
                 : "=r"(r[0]), "=r"(r[1]), "=r"(r[2]), "=r"(r[3]) : "r"(addr));
}
__device__ __forceinline__ void mma16816(float* c, const unsigned* a, const unsigned* b) {
    asm volatile("mma.sync.aligned.m16n8k16.row.col.f32.bf16.bf16.f32 "
                 "{%0,%1,%2,%3}, {%4,%5,%6,%7}, {%8,%9}, {%0,%1,%2,%3};"
                 : "+f"(c[0]), "+f"(c[1]), "+f"(c[2]), "+f"(c[3])
                 : "r"(a[0]), "r"(a[1]), "r"(a[2]), "r"(a[3]), "r"(b[0]), "r"(b[1]));
}
#define CP_ASYNC16(dst, src) \
    asm volatile("cp.async.cg.shared.global [%0], [%1], 16;" :: "r"(dst), "l"(src) : "memory")
#define CP_COMMIT() asm volatile("cp.async.commit_group;" ::: "memory")
#define CP_WAIT(n)  asm volatile("cp.async.wait_group %0;" :: "n"(n) : "memory")

__device__ __forceinline__ void split_store(__nv_bfloat16* base, long o, long K, float v) {
    __nv_bfloat16 hb = __float2bfloat16(v);
    float h = __bfloat162float(hb);
    __nv_bfloat16 lb = __float2bfloat16(v - h);
    base[o]         = hb;
    base[o + K]     = lb;
    base[o + 2 * K] = hb;
}

// ---------------- split prep kernels ----------------
__global__ __launch_bounds__(256)
void prep_act(const float* __restrict__ A, int lda, int K,
              __nv_bfloat16* __restrict__ Ap)
{
    long idx = (long)blockIdx.x * 256 + threadIdx.x;
    long m = idx / K;
    int  k = (int)(idx % K);
    split_store(Ap, m * (3L * K) + k, K, A[m * lda + k]);
}

__global__ __launch_bounds__(256)
void prep_w(const float* __restrict__ W, int N, int K,
            __nv_bfloat16* __restrict__ Wp)
{
    __shared__ float th[32][33];
    __shared__ float tl[32][33];
    int bk = blockIdx.x * 32, bn = blockIdx.y * 32;
    int tx = threadIdx.x & 31, ty = threadIdx.x >> 5;
#pragma unroll
    for (int j = 0; j < 4; j++) {
        int k = bk + ty + j * 8;
        float w = W[(long)k * N + bn + tx];
        float h = __bfloat162float(__float2bfloat16(w));
        th[ty + j * 8][tx] = h;
        tl[ty + j * 8][tx] = w - h;
    }
    __syncthreads();
#pragma unroll
    for (int j = 0; j < 4; j++) {
        int n = bn + ty + j * 8;
        long o = (long)n * (3L * K);
        __nv_bfloat16 hb = __float2bfloat16(th[tx][ty + j * 8]);
        __nv_bfloat16 lb = __float2bfloat16(tl[tx][ty + j * 8]);
        Wp[o + bk + tx]         = hb;
        Wp[o + K + bk + tx]     = hb;
        Wp[o + 2 * K + bk + tx] = lb;
    }
}

__global__ __launch_bounds__(256)
void zero_wp_pad(__nv_bfloat16* __restrict__ Wp)
{
    long i = (long)blockIdx.x * 256 + threadIdx.x;
    Wp[96L * 12288 + i] = __float2bfloat16(0.0f);
}

__global__ __launch_bounds__(256)
void reduce_parts(const float* __restrict__ parts, float* __restrict__ dst,
                  long n, int np)
{
    long i = ((long)blockIdx.x * 256 + threadIdx.x) * 4;
    if (i >= n) return;
    float4 s = *reinterpret_cast<const float4*>(parts + i);
    for (int p = 1; p < np; p++) {
        float4 v = *reinterpret_cast<const float4*>(parts + (long)p * n + i);
        s.x += v.x; s.y += v.y; s.z += v.z; s.w += v.w;
    }
    *reinterpret_cast<float4*>(dst + i) = s;
}

// ---------------- warp-MMA bf16 GEMM: C[M,N] = A'[M,K'] @ W'[N,K']^T -------
// BM=128, BN=128, BK=64 bf16 (128B rows, SW128), 3-stage cp.async ring,
// one __syncthreads per K-tile, 2 CTAs/SM. 8 warps of 32x64.
// blockIdx.z = split-K slice (T tiles each). EPI: 0=none, 1=softplus.
#define STAGES 3
#define STG    32768u
#define GSMEM_TOTAL (STAGES * 32768)

template<int EPI>
__global__ __launch_bounds__(256, 2)
void gemm_mma(const __nv_bfloat16* __restrict__ Ap, int lda,
              const __nv_bfloat16* __restrict__ Bp, int ldb,
              float* __restrict__ C, int ldc, int T, long csplit)
{
    extern __shared__ __align__(1024) char smem[];
    const unsigned sb = smem_u32(smem);
    const int tid  = threadIdx.x;
    const int lane = tid & 31;
    const int wid  = tid >> 5;
    const int wm   = (wid & 3) * 32;   // warp row offset
    const int wn   = (wid >> 2) * 64;  // warp col offset
    const long bm  = (long)blockIdx.y * 128;
    const long bn  = (long)blockIdx.x * 128;

    Ap += (long)blockIdx.z * T * 64;
    Bp += (long)blockIdx.z * T * 64;
    C  += (long)blockIdx.z * csplit;

    const int ldr  = tid >> 3;
    const int ldc8 = (tid & 7) * 8;

    float acc[2][8][4];
#pragma unroll
    for (int i = 0; i < 2; i++)
#pragma unroll
        for (int j = 0; j < 8; j++)
#pragma unroll
            for (int r = 0; r < 4; r++) acc[i][j][r] = 0.0f;

    auto load_tile = [&](int t, int s) {
        const __nv_bfloat16* Ab = Ap + bm * lda + (long)t * 64;
        const __nv_bfloat16* Bb = Bp + bn * ldb + (long)t * 64;
        unsigned oa = sb + (unsigned)s * STG;
        unsigned ob = oa + 16384u;
#pragma unroll
        for (int i = 0; i < 4; i++) {
            int r = ldr + 32 * i;
            unsigned sw = SWZ128((unsigned)(r * 128 + ldc8 * 2));
            CP_ASYNC16(oa + sw, Ab + (long)r * lda + ldc8);
            CP_ASYNC16(ob + sw, Bb + (long)r * ldb + ldc8);
        }
        CP_COMMIT();
    };

#pragma unroll
    for (int s = 0; s < STAGES - 1; s++) {
        if (s < T) load_tile(s, s);
        else       CP_COMMIT();
    }

    const int lr = lane & 15;
    const int lh = (lane >> 4) * 16;

    int stage = 0;
    for (int t = 0; t < T; t++) {
        CP_WAIT(STAGES - 2);
        __syncthreads();
        {
            int tn = t + STAGES - 1;
            int sn = stage + STAGES - 1; if (sn >= STAGES) sn -= STAGES;
            if (tn < T) load_tile(tn, sn);
            else        CP_COMMIT();
        }
        const unsigned sA = sb + (unsigned)stage * STG;
        const unsigned sB = sA + 16384u;
#pragma unroll
        for (int ks = 0; ks < 4; ks++) {
            const int kb = ks * 32;
            unsigned af[2][4];
#pragma unroll
            for (int im = 0; im < 2; im++) {
                unsigned addr = sA + SWZ128((unsigned)((wm + im * 16 + lr) * 128 + kb + lh));
                ldsm4(af[im], addr);
            }
            unsigned bf[8][2];
#pragma unroll
            for (int jn = 0; jn < 4; jn++) {
                unsigned q[4];
                unsigned addr = sB + SWZ128((unsigned)((wn + jn * 16 + lr) * 128 + kb + lh));
                ldsm4(q, addr);
                bf[2 * jn][0]     = q[0];
                bf[2 * jn][1]     = q[2];
                bf[2 * jn + 1][0] = q[1];
                bf[2 * jn + 1][1] = q[3];
            }
#pragma unroll
            for (int im = 0; im < 2; im++)
#pragma unroll
                for (int j = 0; j < 8; j++)
                    mma16816(acc[im][j], af[im], bf[j]);
        }
        if (++stage == STAGES) stage = 0;
    }

    const int gid = lane >> 2;
    const int tig = lane & 3;
#pragma unroll
    for (int im = 0; im < 2; im++) {
        long m0 = bm + wm + im * 16 + gid;
#pragma unroll
        for (int j = 0; j < 8; j++) {
            long n0 = bn + wn + j * 8 + 2 * tig;
            float c0 = acc[im][j][0], c1 = acc[im][j][1];
            float c2 = acc[im][j][2], c3 = acc[im][j][3];
            if (EPI == 1) {
                c0 = softplusf(c0); c1 = softplusf(c1);
                c2 = softplusf(c2); c3 = softplusf(c3);
            }
            *reinterpret_cast<float2*>(C + m0 * ldc + n0)       = make_float2(c0, c1);
            *reinterpret_cast<float2*>(C + (m0 + 8) * ldc + n0) = make_float2(c2, c3);
        }
    }
}

// ---------------- depthwise causal conv(4) + bias + SiLU + u-split ---------
// Each thread computes 4 consecutive t for one d: 7 loads -> 4 outputs.
__global__ __launch_bounds__(256)
void conv_silu_kernel(const float* __restrict__ Wconv,
                      const float* __restrict__ bconv)
{
    long idx = (long)blockIdx.x * 256 + threadIdx.x;   // over B * L/4 * D
    int d  = (int)(idx & (D_INNER - 1));
    int t4 = (int)((idx >> 12) & (L_SEQ / 4 - 1));
    int b  = (int)(idx >> 20);
    int t0 = t4 * 4;

    float w0 = Wconv[d * 4 + 0], w1 = Wconv[d * 4 + 1];
    float w2 = Wconv[d * 4 + 2], w3 = Wconv[d * 4 + 3];
    float bc = bconv[d];

    const long rowbase = (long)(b * L_SEQ) * (2 * D_INNER) + d;
    float v[7];
#pragma unroll
    for (int i = 0; i < 7; i++) {
        int tt = t0 - 3 + i;
        v[i] = (tt >= 0) ? g_xz[rowbase + (long)tt * (2 * D_INNER)] : 0.0f;
    }

    long m = (long)(b * L_SEQ + t0);
#pragma unroll
    for (int q = 0; q < 4; q++) {
        float acc = bc;
        acc = fmaf(v[q],     w0, acc);
        acc = fmaf(v[q + 1], w1, acc);
        acc = fmaf(v[q + 2], w2, acc);
        acc = fmaf(v[q + 3], w3, acc);
        float uu = siluf(acc);
        g_u[(m + q) * D_INNER + d] = uu;
        split_store(g_ap, (m + q) * (3L * D_INNER) + d, D_INNER, uu);
    }
}

// ---------------- selective scan + epilogue + y-split ----------------------
__global__ __launch_bounds__(128)
void scan_kernel(const float* __restrict__ A_log,
                 const float* __restrict__ Dp)
{
    extern __shared__ __align__(16) float sBC[];   // [L_SEQ][32]
    const int b = blockIdx.x >> 5;
    const int d = ((blockIdx.x & 31) << 7) + threadIdx.x;
    const long base = (long)b * L_SEQ;

    for (int i = threadIdx.x * 4; i < L_SEQ * 32; i += 128 * 4) {
        int t = i >> 5, c = i & 31;
        *reinterpret_cast<float4*>(&sBC[i]) =
            *reinterpret_cast<const float4*>(&g_xdbl[(base + t) * XDBL_LD + DT_RANK + c]);
    }
    __syncthreads();

    float A[N_STATE];
#pragma unroll
    for (int n = 0; n < N_STATE; n++)
        A[n] = -__expf(A_log[d * N_STATE + n]);
    const float A1 = A[0];
    bool fast = true;
#pragma unroll
    for (int n = 1; n < N_STATE; n++)
        fast = fast && (fabsf(A[n] - (float)(n + 1) * A1) <= 1e-4f * fabsf(A[n]) + 1e-30f);

    const float Dd = Dp[d];
    float h[N_STATE];
#pragma unroll
    for (int n = 0; n < N_STATE; n++) h[n] = 0.0f;

    float pdt[4], pu[4], pr[4];
#pragma unroll
    for (int q = 0; q < 4; q++) {
        long row = base + q;
        pdt[q] = g_delta[row * D_INNER + d];
        pu[q]  = g_u[row * D_INNER + d];
        pr[q]  = g_xz[row * (2 * D_INNER) + D_INNER + d];
    }

    for (int t0 = 0; t0 < L_SEQ; t0 += 4) {
        float cdt[4], cu[4], cr[4];
#pragma unroll
        for (int q = 0; q < 4; q++) { cdt[q] = pdt[q]; cu[q] = pu[q]; cr[q] = pr[q]; }
        if (t0 + 4 < L_SEQ) {
#pragma unroll
            for (int q = 0; q < 4; q++) {
                long row = base + t0 + 4 + q;
                pdt[q] = g_delta[row * D_INNER + d];
                pu[q]  = g_u[row * D_INNER + d];
                pr[q]  = g_xz[row * (2 * D_INNER) + D_INNER + d];
            }
        }
#pragma unroll
        for (int q = 0; q < 4; q++) {
            const int t = t0 + q;
            const float* BC = &sBC[t * 32];
            const float dt = cdt[q], uu = cu[q], rr = cr[q];
            const float dtu = dt * uu;
            float yv = 0.0f;
            if (fast) {
                // pw[n] = p^(n+1) via squaring tree (depth ~4)
                const float p1 = __expf(dt * A1);
                const float p2 = p1 * p1;
                const float p4 = p2 * p2;
                const float p8 = p4 * p4;
                float pw[N_STATE];
                pw[0] = p1;        pw[1] = p2;        pw[2] = p2 * p1;   pw[3] = p4;
                pw[4] = p4 * p1;   pw[5] = p4 * p2;   pw[6] = p4 * pw[2];pw[7] = p8;
                pw[8] = p8 * p1;   pw[9] = p8 * p2;   pw[10] = p8 * pw[2]; pw[11] = p8 * p4;
                pw[12] = p8 * pw[4]; pw[13] = p8 * pw[5]; pw[14] = p8 * pw[6]; pw[15] = p8 * p8;
#pragma unroll
                for (int n = 0; n < N_STATE; n++) {
                    h[n] = fmaf(pw[n], h[n], dtu * BC[n]);
                    yv = fmaf(h[n], BC[N_STATE + n], yv);
                }
            } else {
#pragma unroll
                for (int n = 0; n < N_STATE; n++) {
                    float da = __expf(dt * A[n]);
                    h[n] = fmaf(da, h[n], dtu * BC[n]);
                    yv = fmaf(h[n], BC[N_STATE + n], yv);
                }
            }
            float yo = (yv + uu * Dd) * siluf(rr);
            split_store(g_ap, (base + t) * (3L * D_INNER) + d, D_INNER, yo);
        }
    }
}

// ---------------- launcher ----------------
extern "C" void kernel_launch(void* const* d_in, const int* in_sizes, int n_in,
                              void* d_out, int out_size)
{
    (void)in_sizes; (void)n_in; (void)out_size;
    const float* x     = (const float*)d_in[0];
    const float* Win   = (const float*)d_in[1];
    const float* Wconv = (const float*)d_in[2];
    const float* bconv = (const float*)d_in[3];
    const float* Wx    = (const float*)d_in[4];
    const float* Wdt   = (const float*)d_in[5];
    const float* A_log = (const float*)d_in[6];
    const float* D     = (const float*)d_in[7];
    const float* Wout  = (const float*)d_in[8];
    float* out = (float*)d_out;

    float *xz, *xdbl, *delta, *partx, *party;
    __nv_bfloat16 *ap, *ap2, *wp;
    cudaGetSymbolAddress((void**)&xz,    g_xz);
    cudaGetSymbolAddress((void**)&xdbl,  g_xdbl);
    cudaGetSymbolAddress((void**)&delta, g_delta);
    cudaGetSymbolAddress((void**)&partx, g_partx);
    cudaGetSymbolAddress((void**)&party, g_party);
    cudaGetSymbolAddress((void**)&ap,    g_ap);
    cudaGetSymbolAddress((void**)&ap2,   g_ap2);
    cudaGetSymbolAddress((void**)&wp,    g_wp);

    cudaFuncSetAttribute(gemm_mma<0>, cudaFuncAttributeMaxDynamicSharedMemorySize, GSMEM_TOTAL);
    cudaFuncSetAttribute(gemm_mma<1>, cudaFuncAttributeMaxDynamicSharedMemorySize, GSMEM_TOTAL);
    const int scan_smem = L_SEQ * 32 * sizeof(float);
    cudaFuncSetAttribute(scan_kernel, cudaFuncAttributeMaxDynamicSharedMemorySize, scan_smem);

    // ---- GEMM1: xz = x @ Win   (2048 x 8192, K'=3072, T=48) ----
    prep_w<<<dim3(D_MODEL / 32, 2 * D_INNER / 32), 256>>>(Win, 2 * D_INNER, D_MODEL, wp);
    prep_act<<<(M_ROWS * D_MODEL) / 256, 256>>>(x, D_MODEL, D_MODEL, ap);
    gemm_mma<0><<<dim3(2 * D_INNER / 128, M_ROWS / 128, 1), 256, GSMEM_TOTAL>>>(
        ap, 3 * D_MODEL, wp, 3 * D_MODEL, xz, 2 * D_INNER, 48, 0);

    // ---- conv + SiLU -> u (fp32) + u' (split, into ap) ----
    conv_silu_kernel<<<(B_SZ * (L_SEQ / 4) * D_INNER) / 256, 256>>>(Wconv, bconv);

    // ---- x_dbl = u @ Wx   (2048 x 128pad, K'=12288; split-K x16, T=12) ----
    prep_w<<<dim3(D_INNER / 32, 96 / 32), 256>>>(Wx, 96, D_INNER, wp);
    zero_wp_pad<<<(32 * 12288) / 256, 256>>>(wp);
    gemm_mma<0><<<dim3(1, M_ROWS / 128, 16), 256, GSMEM_TOTAL>>>(
        ap, 3 * D_INNER, wp, 3 * D_INNER, partx, XDBL_LD, 12, (long)M_ROWS * XDBL_LD);
    reduce_parts<<<(M_ROWS * XDBL_LD) / 1024, 256>>>(partx, xdbl, (long)M_ROWS * XDBL_LD, 16);

    // ---- delta = softplus(x_dbl[:, :64] @ Wdt)  (2048 x 4096, K'=192, T=3) ----
    prep_w<<<dim3(DT_RANK / 32, D_INNER / 32), 256>>>(Wdt, D_INNER, DT_RANK, wp);
    prep_act<<<(M_ROWS * DT_RANK) / 256, 256>>>(xdbl, XDBL_LD, DT_RANK, ap2);
    gemm_mma<1><<<dim3(D_INNER / 128, M_ROWS / 128, 1), 256, GSMEM_TOTAL>>>(
        ap2, 3 * DT_RANK, wp, 3 * DT_RANK, delta, D_INNER, 3, 0);

    // ---- selective scan + epilogue -> y' (split, into ap) ----
    prep_w<<<dim3(D_INNER / 32, D_MODEL / 32), 256>>>(Wout, D_MODEL, D_INNER, wp);
    scan_kernel<<<64, 128, scan_smem>>>(A_log, D);

    // ---- out = y @ Wout   (2048 x 1024, K'=12288; split-K x2, T=96) ----
    gemm_mma<0><<<dim3(D_MODEL / 128, M_ROWS / 128, 2), 256, GSMEM_TOTAL>>>(
        ap, 3 * D_INNER, wp, 3 * D_INNER, party, D_MODEL, 96, (long)M_ROWS * D_MODEL);
    reduce_parts<<<(M_ROWS * D_MODEL) / 1024, 256>>>(party, out, (long)M_ROWS * D_MODEL, 2);
}

// round 12
// speedup vs baseline: 1.0555x; 1.0550x over previous
#include <cuda_runtime.h>
#include <cuda_bf16.h>

// ---------------- problem constants ----------------
#define B_SZ     2
#define L_SEQ    1024
#define D_MODEL  1024
#define D_INNER  4096
#define N_STATE  16
#define DT_RANK  64
#define M_ROWS   (B_SZ * L_SEQ)          // 2048
#define XDBL_LD  128                     // padded x_dbl leading dim

// ---------------- scratch (device globals; no allocs allowed) ----------------
__device__ float g_xz   [(long)M_ROWS * 2 * D_INNER]; // 2048 x 8192  (xc | res)
__device__ float g_u    [(long)M_ROWS * D_INNER];     // 2048 x 4096 (fp32 for scan)
__device__ float g_xdbl [(long)M_ROWS * XDBL_LD];     // 2048 x 128 (cols 96..127 pad)
__device__ float g_delta[(long)M_ROWS * D_INNER];     // 2048 x 4096
__device__ float g_partx[8L * M_ROWS * XDBL_LD];      // split-K partials (xdbl)
__device__ float g_party[4L * M_ROWS * D_MODEL];      // split-K partials (out)
__device__ __nv_bfloat16 g_ap [(long)M_ROWS * 3 * D_INNER];  // u'/y' split
__device__ __nv_bfloat16 g_ap2[(long)M_ROWS * 3 * DT_RANK];  // delta-GEMM A'
__device__ __nv_bfloat16 g_wp [(long)(2 * D_INNER) * 3 * D_MODEL];

// ---------------- helpers ----------------
__device__ __forceinline__ float siluf(float x) { return x / (1.0f + __expf(-x)); }
__device__ __forceinline__ float softplusf(float x) {
    return (x > 0.0f) ? (x + log1pf(expf(-x))) : log1pf(expf(x));
}
__device__ __forceinline__ unsigned smem_u32(const void* p) {
    unsigned a;
    asm("{ .reg .u64 t; cvta.to.shared.u64 t, %1; cvt.u32.u64 %0, t; }" : "=r"(a) : "l"(p));
    return a;
}
#define SWZ128(o) ((o) ^ (((o) >> 3) & 0x70))

__device__ __forceinline__ void ldsm4(unsigned* r, unsigned addr) {
    asm volatile("ldmatrix.sync.aligned.m8n8.x4.shared.b16 {%0,%1,%2,%3}, [%4];"
                 : "=r"(r[0]), "=r"(r[1]), "=r"(r[2]), "=r"(r[3]) : "r"(addr));
}
__device__ __forceinline__ void mma16816(float* c, const unsigned* a, const unsigned* b) {
    asm volatile("mma.sync.aligned.m16n8k16.row.col.f32.bf16.bf16.f32 "
                 "{%0,%1,%2,%3}, {%4,%5,%6,%7}, {%8,%9}, {%0,%1,%2,%3};"
                 : "+f"(c[0]), "+f"(c[1]), "+f"(c[2]), "+f"(c[3])
                 : "r"(a[0]), "r"(a[1]), "r"(a[2]), "r"(a[3]), "r"(b[0]), "r"(b[1]));
}
#define CP_ASYNC16(dst, src) \
    asm volatile("cp.async.cg.shared.global [%0], [%1], 16;" :: "r"(dst), "l"(src) : "memory")
#define CP_COMMIT() asm volatile("cp.async.commit_group;" ::: "memory")
#define CP_WAIT(n)  asm volatile("cp.async.wait_group %0;" :: "n"(n) : "memory")

__device__ __forceinline__ void split_store(__nv_bfloat16* base, long o, long K, float v) {
    __nv_bfloat16 hb = __float2bfloat16(v);
    float h = __bfloat162float(hb);
    __nv_bfloat16 lb = __float2bfloat16(v - h);
    base[o]         = hb;
    base[o + K]     = lb;
    base[o + 2 * K] = hb;
}

// ---------------- split prep kernels ----------------
__global__ __launch_bounds__(256)
void prep_act(const float* __restrict__ A, int lda, int K,
              __nv_bfloat16* __restrict__ Ap)
{
    long idx = (long)blockIdx.x * 256 + threadIdx.x;
    long m = idx / K;
    int  k = (int)(idx % K);
    split_store(Ap, m * (3L * K) + k, K, A[m * lda + k]);
}

__global__ __launch_bounds__(256)
void prep_w(const float* __restrict__ W, int N, int K,
            __nv_bfloat16* __restrict__ Wp)
{
    __shared__ float th[32][33];
    __shared__ float tl[32][33];
    int bk = blockIdx.x * 32, bn = blockIdx.y * 32;
    int tx = threadIdx.x & 31, ty = threadIdx.x >> 5;
#pragma unroll
    for (int j = 0; j < 4; j++) {
        int k = bk + ty + j * 8;
        float w = W[(long)k * N + bn + tx];
        float h = __bfloat162float(__float2bfloat16(w));
        th[ty + j * 8][tx] = h;
        tl[ty + j * 8][tx] = w - h;
    }
    __syncthreads();
#pragma unroll
    for (int j = 0; j < 4; j++) {
        int n = bn + ty + j * 8;
        long o = (long)n * (3L * K);
        __nv_bfloat16 hb = __float2bfloat16(th[tx][ty + j * 8]);
        __nv_bfloat16 lb = __float2bfloat16(tl[tx][ty + j * 8]);
        Wp[o + bk + tx]         = hb;
        Wp[o + K + bk + tx]     = hb;
        Wp[o + 2 * K + bk + tx] = lb;
    }
}

__global__ __launch_bounds__(256)
void zero_wp_pad(__nv_bfloat16* __restrict__ Wp)
{
    long i = (long)blockIdx.x * 256 + threadIdx.x;
    Wp[96L * 12288 + i] = __float2bfloat16(0.0f);
}

__global__ __launch_bounds__(256)
void reduce_parts(const float* __restrict__ parts, float* __restrict__ dst,
                  long n, int np)
{
    long i = ((long)blockIdx.x * 256 + threadIdx.x) * 4;
    if (i >= n) return;
    float4 s = *reinterpret_cast<const float4*>(parts + i);
    for (int p = 1; p < np; p++) {
        float4 v = *reinterpret_cast<const float4*>(parts + (long)p * n + i);
        s.x += v.x; s.y += v.y; s.z += v.z; s.w += v.w;
    }
    *reinterpret_cast<float4*>(dst + i) = s;
}

// ---------------- warp-MMA bf16 GEMM: C[M,N] = A'[M,K'] @ W'[N,K']^T -------
// BM=128, BN=128, BK=64 bf16 (128B rows, SW128), 3-stage cp.async ring,
// one __syncthreads per K-tile, 2 CTAs/SM. 8 warps of 32x64.
// blockIdx.z = split-K slice (T tiles each). EPI: 0=none, 1=softplus.
#define STAGES 3
#define STG    32768u
#define GSMEM_TOTAL (STAGES * 32768)

template<int EPI>
__global__ __launch_bounds__(256, 2)
void gemm_mma(const __nv_bfloat16* __restrict__ Ap, int lda,
              const __nv_bfloat16* __restrict__ Bp, int ldb,
              float* __restrict__ C, int ldc, int T, long csplit)
{
    extern __shared__ __align__(1024) char smem[];
    const unsigned sb = smem_u32(smem);
    const int tid  = threadIdx.x;
    const int lane = tid & 31;
    const int wid  = tid >> 5;
    const int wm   = (wid & 3) * 32;   // warp row offset
    const int wn   = (wid >> 2) * 64;  // warp col offset
    const long bm  = (long)blockIdx.y * 128;
    const long bn  = (long)blockIdx.x * 128;

    Ap += (long)blockIdx.z * T * 64;
    Bp += (long)blockIdx.z * T * 64;
    C  += (long)blockIdx.z * csplit;

    const int ldr  = tid >> 3;
    const int ldc8 = (tid & 7) * 8;

    float acc[2][8][4];
#pragma unroll
    for (int i = 0; i < 2; i++)
#pragma unroll
        for (int j = 0; j < 8; j++)
#pragma unroll
            for (int r = 0; r < 4; r++) acc[i][j][r] = 0.0f;

    auto load_tile = [&](int t, int s) {
        const __nv_bfloat16* Ab = Ap + bm * lda + (long)t * 64;
        const __nv_bfloat16* Bb = Bp + bn * ldb + (long)t * 64;
        unsigned oa = sb + (unsigned)s * STG;
        unsigned ob = oa + 16384u;
#pragma unroll
        for (int i = 0; i < 4; i++) {
            int r = ldr + 32 * i;
            unsigned sw = SWZ128((unsigned)(r * 128 + ldc8 * 2));
            CP_ASYNC16(oa + sw, Ab + (long)r * lda + ldc8);
            CP_ASYNC16(ob + sw, Bb + (long)r * ldb + ldc8);
        }
        CP_COMMIT();
    };

#pragma unroll
    for (int s = 0; s < STAGES - 1; s++) {
        if (s < T) load_tile(s, s);
        else       CP_COMMIT();
    }

    const int lr = lane & 15;
    const int lh = (lane >> 4) * 16;

    int stage = 0;
    for (int t = 0; t < T; t++) {
        CP_WAIT(STAGES - 2);
        __syncthreads();
        {
            int tn = t + STAGES - 1;
            int sn = stage + STAGES - 1; if (sn >= STAGES) sn -= STAGES;
            if (tn < T) load_tile(tn, sn);
            else        CP_COMMIT();
        }
        const unsigned sA = sb + (unsigned)stage * STG;
        const unsigned sB = sA + 16384u;
#pragma unroll
        for (int ks = 0; ks < 4; ks++) {
            const int kb = ks * 32;
            unsigned af[2][4];
#pragma unroll
            for (int im = 0; im < 2; im++) {
                unsigned addr = sA + SWZ128((unsigned)((wm + im * 16 + lr) * 128 + kb + lh));
                ldsm4(af[im], addr);
            }
            unsigned bf[8][2];
#pragma unroll
            for (int jn = 0; jn < 4; jn++) {
                unsigned q[4];
                unsigned addr = sB + SWZ128((unsigned)((wn + jn * 16 + lr) * 128 + kb + lh));
                ldsm4(q, addr);
                bf[2 * jn][0]     = q[0];
                bf[2 * jn][1]     = q[2];
                bf[2 * jn + 1][0] = q[1];
                bf[2 * jn + 1][1] = q[3];
            }
#pragma unroll
            for (int im = 0; im < 2; im++)
#pragma unroll
                for (int j = 0; j < 8; j++)
                    mma16816(acc[im][j], af[im], bf[j]);
        }
        if (++stage == STAGES) stage = 0;
    }

    const int gid = lane >> 2;
    const int tig = lane & 3;
#pragma unroll
    for (int im = 0; im < 2; im++) {
        long m0 = bm + wm + im * 16 + gid;
#pragma unroll
        for (int j = 0; j < 8; j++) {
            long n0 = bn + wn + j * 8 + 2 * tig;
            float c0 = acc[im][j][0], c1 = acc[im][j][1];
            float c2 = acc[im][j][2], c3 = acc[im][j][3];
            if (EPI == 1) {
                c0 = softplusf(c0); c1 = softplusf(c1);
                c2 = softplusf(c2); c3 = softplusf(c3);
            }
            *reinterpret_cast<float2*>(C + m0 * ldc + n0)       = make_float2(c0, c1);
            *reinterpret_cast<float2*>(C + (m0 + 8) * ldc + n0) = make_float2(c2, c3);
        }
    }
}

// ---------------- depthwise causal conv(4) + bias + SiLU + u-split ---------
// Each thread computes 4 consecutive t for one d: 7 loads -> 4 outputs.
__global__ __launch_bounds__(256)
void conv_silu_kernel(const float* __restrict__ Wconv,
                      const float* __restrict__ bconv)
{
    long idx = (long)blockIdx.x * 256 + threadIdx.x;   // over B * L/4 * D
    int d  = (int)(idx & (D_INNER - 1));
    int t4 = (int)((idx >> 12) & (L_SEQ / 4 - 1));
    int b  = (int)(idx >> 20);
    int t0 = t4 * 4;

    float w0 = Wconv[d * 4 + 0], w1 = Wconv[d * 4 + 1];
    float w2 = Wconv[d * 4 + 2], w3 = Wconv[d * 4 + 3];
    float bc = bconv[d];

    const long rowbase = (long)(b * L_SEQ) * (2 * D_INNER) + d;
    float v[7];
#pragma unroll
    for (int i = 0; i < 7; i++) {
        int tt = t0 - 3 + i;
        v[i] = (tt >= 0) ? g_xz[rowbase + (long)tt * (2 * D_INNER)] : 0.0f;
    }

    long m = (long)(b * L_SEQ + t0);
#pragma unroll
    for (int q = 0; q < 4; q++) {
        float acc = bc;
        acc = fmaf(v[q],     w0, acc);
        acc = fmaf(v[q + 1], w1, acc);
        acc = fmaf(v[q + 2], w2, acc);
        acc = fmaf(v[q + 3], w3, acc);
        float uu = siluf(acc);
        g_u[(m + q) * D_INNER + d] = uu;
        split_store(g_ap, (m + q) * (3L * D_INNER) + d, D_INNER, uu);
    }
}

// ---------------- selective scan + epilogue + y-split ----------------------
__global__ __launch_bounds__(128)
void scan_kernel(const float* __restrict__ A_log,
                 const float* __restrict__ Dp)
{
    extern __shared__ __align__(16) float sBC[];   // [L_SEQ][32]
    const int b = blockIdx.x >> 5;
    const int d = ((blockIdx.x & 31) << 7) + threadIdx.x;
    const long base = (long)b * L_SEQ;

    for (int i = threadIdx.x * 4; i < L_SEQ * 32; i += 128 * 4) {
        int t = i >> 5, c = i & 31;
        *reinterpret_cast<float4*>(&sBC[i]) =
            *reinterpret_cast<const float4*>(&g_xdbl[(base + t) * XDBL_LD + DT_RANK + c]);
    }
    __syncthreads();

    float A[N_STATE];
#pragma unroll
    for (int n = 0; n < N_STATE; n++)
        A[n] = -__expf(A_log[d * N_STATE + n]);
    const float A1 = A[0];
    bool fast = true;
#pragma unroll
    for (int n = 1; n < N_STATE; n++)
        fast = fast && (fabsf(A[n] - (float)(n + 1) * A1) <= 1e-4f * fabsf(A[n]) + 1e-30f);

    const float Dd = Dp[d];
    float h[N_STATE];
#pragma unroll
    for (int n = 0; n < N_STATE; n++) h[n] = 0.0f;

    float pdt[4], pu[4], pr[4];
#pragma unroll
    for (int q = 0; q < 4; q++) {
        long row = base + q;
        pdt[q] = g_delta[row * D_INNER + d];
        pu[q]  = g_u[row * D_INNER + d];
        pr[q]  = g_xz[row * (2 * D_INNER) + D_INNER + d];
    }

    for (int t0 = 0; t0 < L_SEQ; t0 += 4) {
        float cdt[4], cu[4], cr[4];
#pragma unroll
        for (int q = 0; q < 4; q++) { cdt[q] = pdt[q]; cu[q] = pu[q]; cr[q] = pr[q]; }
        if (t0 + 4 < L_SEQ) {
#pragma unroll
            for (int q = 0; q < 4; q++) {
                long row = base + t0 + 4 + q;
                pdt[q] = g_delta[row * D_INNER + d];
                pu[q]  = g_u[row * D_INNER + d];
                pr[q]  = g_xz[row * (2 * D_INNER) + D_INNER + d];
            }
        }
#pragma unroll
        for (int q = 0; q < 4; q++) {
            const int t = t0 + q;
            const float* BC = &sBC[t * 32];
            const float dt = cdt[q], uu = cu[q], rr = cr[q];
            const float dtu = dt * uu;
            float yv = 0.0f;
            if (fast) {
                const float p = __expf(dt * A1);
                float da = p;
#pragma unroll
                for (int n = 0; n < N_STATE; n++) {
                    h[n] = fmaf(da, h[n], dtu * BC[n]);
                    yv = fmaf(h[n], BC[N_STATE + n], yv);
                    da *= p;
                }
            } else {
#pragma unroll
                for (int n = 0; n < N_STATE; n++) {
                    float da = __expf(dt * A[n]);
                    h[n] = fmaf(da, h[n], dtu * BC[n]);
                    yv = fmaf(h[n], BC[N_STATE + n], yv);
                }
            }
            float yo = (yv + uu * Dd) * siluf(rr);
            split_store(g_ap, (base + t) * (3L * D_INNER) + d, D_INNER, yo);
        }
    }
}

// ---------------- launcher ----------------
extern "C" void kernel_launch(void* const* d_in, const int* in_sizes, int n_in,
                              void* d_out, int out_size)
{
    (void)in_sizes; (void)n_in; (void)out_size;
    const float* x     = (const float*)d_in[0];
    const float* Win   = (const float*)d_in[1];
    const float* Wconv = (const float*)d_in[2];
    const float* bconv = (const float*)d_in[3];
    const float* Wx    = (const float*)d_in[4];
    const float* Wdt   = (const float*)d_in[5];
    const float* A_log = (const float*)d_in[6];
    const float* D     = (const float*)d_in[7];
    const float* Wout  = (const float*)d_in[8];
    float* out = (float*)d_out;

    float *xz, *xdbl, *delta, *partx, *party;
    __nv_bfloat16 *ap, *ap2, *wp;
    cudaGetSymbolAddress((void**)&xz,    g_xz);
    cudaGetSymbolAddress((void**)&xdbl,  g_xdbl);
    cudaGetSymbolAddress((void**)&delta, g_delta);
    cudaGetSymbolAddress((void**)&partx, g_partx);
    cudaGetSymbolAddress((void**)&party, g_party);
    cudaGetSymbolAddress((void**)&ap,    g_ap);
    cudaGetSymbolAddress((void**)&ap2,   g_ap2);
    cudaGetSymbolAddress((void**)&wp,    g_wp);

    cudaFuncSetAttribute(gemm_mma<0>, cudaFuncAttributeMaxDynamicSharedMemorySize, GSMEM_TOTAL);
    cudaFuncSetAttribute(gemm_mma<1>, cudaFuncAttributeMaxDynamicSharedMemorySize, GSMEM_TOTAL);
    const int scan_smem = L_SEQ * 32 * sizeof(float);
    cudaFuncSetAttribute(scan_kernel, cudaFuncAttributeMaxDynamicSharedMemorySize, scan_smem);

    // ---- GEMM1: xz = x @ Win   (2048 x 8192, K'=3072, T=48) ----
    prep_w<<<dim3(D_MODEL / 32, 2 * D_INNER / 32), 256>>>(Win, 2 * D_INNER, D_MODEL, wp);
    prep_act<<<(M_ROWS * D_MODEL) / 256, 256>>>(x, D_MODEL, D_MODEL, ap);
    gemm_mma<0><<<dim3(2 * D_INNER / 128, M_ROWS / 128, 1), 256, GSMEM_TOTAL>>>(
        ap, 3 * D_MODEL, wp, 3 * D_MODEL, xz, 2 * D_INNER, 48, 0);

    // ---- conv + SiLU -> u (fp32) + u' (split, into ap) ----
    conv_silu_kernel<<<(B_SZ * (L_SEQ / 4) * D_INNER) / 256, 256>>>(Wconv, bconv);

    // ---- x_dbl = u @ Wx   (2048 x 128pad, K'=12288; split-K x8, T=24) ----
    prep_w<<<dim3(D_INNER / 32, 96 / 32), 256>>>(Wx, 96, D_INNER, wp);
    zero_wp_pad<<<(32 * 12288) / 256, 256>>>(wp);
    gemm_mma<0><<<dim3(1, M_ROWS / 128, 8), 256, GSMEM_TOTAL>>>(
        ap, 3 * D_INNER, wp, 3 * D_INNER, partx, XDBL_LD, 24, (long)M_ROWS * XDBL_LD);
    reduce_parts<<<(M_ROWS * XDBL_LD) / 1024, 256>>>(partx, xdbl, (long)M_ROWS * XDBL_LD, 8);

    // ---- delta = softplus(x_dbl[:, :64] @ Wdt)  (2048 x 4096, K'=192, T=3) ----
    prep_w<<<dim3(DT_RANK / 32, D_INNER / 32), 256>>>(Wdt, D_INNER, DT_RANK, wp);
    prep_act<<<(M_ROWS * DT_RANK) / 256, 256>>>(xdbl, XDBL_LD, DT_RANK, ap2);
    gemm_mma<1><<<dim3(D_INNER / 128, M_ROWS / 128, 1), 256, GSMEM_TOTAL>>>(
        ap2, 3 * DT_RANK, wp, 3 * DT_RANK, delta, D_INNER, 3, 0);

    // ---- selective scan + epilogue -> y' (split, into ap) ----
    prep_w<<<dim3(D_INNER / 32, D_MODEL / 32), 256>>>(Wout, D_MODEL, D_INNER, wp);
    scan_kernel<<<64, 128, scan_smem>>>(A_log, D);

    // ---- out = y @ Wout   (2048 x 1024, K'=12288; split-K x4, T=48) ----
    gemm_mma<0><<<dim3(D_MODEL / 128, M_ROWS / 128, 4), 256, GSMEM_TOTAL>>>(
        ap, 3 * D_INNER, wp, 3 * D_INNER, party, D_MODEL, 48, (long)M_ROWS * D_MODEL);
    reduce_parts<<<(M_ROWS * D_MODEL) / 1024, 256>>>(party, out, (long)M_ROWS * D_MODEL, 4);
}

// round 13
// speedup vs baseline: 1.2674x; 1.2008x over previous
#include <cuda_runtime.h>
#include <cuda_fp16.h>

// ---------------- problem constants ----------------
#define B_SZ     2
#define L_SEQ    1024
#define D_MODEL  1024
#define D_INNER  4096
#define N_STATE  16
#define DT_RANK  64
#define M_ROWS   (B_SZ * L_SEQ)          // 2048
#define XDBL_LD  128                     // padded x_dbl leading dim

// ---------------- scratch (device globals; no allocs allowed) ----------------
__device__ float g_xz   [(long)M_ROWS * 2 * D_INNER]; // 2048 x 8192  (xc | res)
__device__ float g_u    [(long)M_ROWS * D_INNER];     // 2048 x 4096 (fp32 for scan)
__device__ float g_xdbl [(long)M_ROWS * XDBL_LD];     // 2048 x 128 (cols 96..127 pad)
__device__ float g_delta[(long)M_ROWS * D_INNER];     // 2048 x 4096
__device__ float g_partx[8L * M_ROWS * XDBL_LD];      // split-K partials (xdbl)
__device__ float g_party[4L * M_ROWS * D_MODEL];      // split-K partials (out)
__device__ __half g_ap [(long)M_ROWS * 2 * D_INNER];  // u'/y' split [Ah|Al]
__device__ __half g_ap2[(long)M_ROWS * 2 * DT_RANK];  // delta-GEMM A'
__device__ __half g_wp [(long)(2 * D_INNER) * 2 * D_MODEL]; // W' = [Wh|Wh]

// ---------------- helpers ----------------
__device__ __forceinline__ float siluf(float x) { return x / (1.0f + __expf(-x)); }
__device__ __forceinline__ float softplusf(float x) {
    return (x > 0.0f) ? (x + log1pf(expf(-x))) : log1pf(expf(x));
}
__device__ __forceinline__ unsigned smem_u32(const void* p) {
    unsigned a;
    asm("{ .reg .u64 t; cvta.to.shared.u64 t, %1; cvt.u32.u64 %0, t; }" : "=r"(a) : "l"(p));
    return a;
}
#define SWZ128(o) ((o) ^ (((o) >> 3) & 0x70))

__device__ __forceinline__ void ldsm4(unsigned* r, unsigned addr) {
    asm volatile("ldmatrix.sync.aligned.m8n8.x4.shared.b16 {%0,%1,%2,%3}, [%4];"
                 : "=r"(r[0]), "=r"(r[1]), "=r"(r[2]), "=r"(r[3]) : "r"(addr));
}
__device__ __forceinline__ void mma16816(float* c, const unsigned* a, const unsigned* b) {
    asm volatile("mma.sync.aligned.m16n8k16.row.col.f32.f16.f16.f32 "
                 "{%0,%1,%2,%3}, {%4,%5,%6,%7}, {%8,%9}, {%0,%1,%2,%3};"
                 : "+f"(c[0]), "+f"(c[1]), "+f"(c[2]), "+f"(c[3])
                 : "r"(a[0]), "r"(a[1]), "r"(a[2]), "r"(a[3]), "r"(b[0]), "r"(b[1]));
}
#define CP_ASYNC16(dst, src) \
    asm volatile("cp.async.cg.shared.global [%0], [%1], 16;" :: "r"(dst), "l"(src) : "memory")
#define CP_COMMIT() asm volatile("cp.async.commit_group;" ::: "memory")
#define CP_WAIT(n)  asm volatile("cp.async.wait_group %0;" :: "n"(n) : "memory")

// fp16 2-term activation split: a = ah + al (exact to ~2^-22)
__device__ __forceinline__ void split_store(__half* base, long o, long K, float v) {
    __half hb = __float2half_rn(v);
    __half lb = __float2half_rn(v - __half2float(hb));
    base[o]     = hb;
    base[o + K] = lb;
}

// ---------------- split prep kernels ----------------
__global__ __launch_bounds__(256)
void prep_act(const float* __restrict__ A, int lda, int K,
              __half* __restrict__ Ap)
{
    long idx = (long)blockIdx.x * 256 + threadIdx.x;
    long m = idx / K;
    int  k = (int)(idx % K);
    split_store(Ap, m * (2L * K) + k, K, A[m * lda + k]);
}

// W[K,N] -> W'[N,2K]: both segments = Wh (fp16 quantized), transposed
__global__ __launch_bounds__(256)
void prep_w(const float* __restrict__ W, int N, int K,
            __half* __restrict__ Wp)
{
    __shared__ float th[32][33];
    int bk = blockIdx.x * 32, bn = blockIdx.y * 32;
    int tx = threadIdx.x & 31, ty = threadIdx.x >> 5;
#pragma unroll
    for (int j = 0; j < 4; j++) {
        int k = bk + ty + j * 8;
        th[ty + j * 8][tx] = W[(long)k * N + bn + tx];
    }
    __syncthreads();
#pragma unroll
    for (int j = 0; j < 4; j++) {
        int n = bn + ty + j * 8;
        long o = (long)n * (2L * K);
        __half hb = __float2half_rn(th[tx][ty + j * 8]);
        Wp[o + bk + tx]     = hb;
        Wp[o + K + bk + tx] = hb;
    }
}

// zero rows 96..127 of Wx' (N padded to 128, K'=8192)
__global__ __launch_bounds__(256)
void zero_wp_pad(__half* __restrict__ Wp)
{
    long i = (long)blockIdx.x * 256 + threadIdx.x;
    Wp[96L * 8192 + i] = __float2half_rn(0.0f);
}

__global__ __launch_bounds__(256)
void reduce_parts(const float* __restrict__ parts, float* __restrict__ dst,
                  long n, int np)
{
    long i = ((long)blockIdx.x * 256 + threadIdx.x) * 4;
    if (i >= n) return;
    float4 s = *reinterpret_cast<const float4*>(parts + i);
    for (int p = 1; p < np; p++) {
        float4 v = *reinterpret_cast<const float4*>(parts + (long)p * n + i);
        s.x += v.x; s.y += v.y; s.z += v.z; s.w += v.w;
    }
    *reinterpret_cast<float4*>(dst + i) = s;
}

// ---------------- warp-MMA fp16 GEMM: C[M,N] = A'[M,K'] @ W'[N,K']^T -------
// BM=128, BN=128, BK=64 fp16 (128B rows, SW128), 3-stage cp.async ring,
// one __syncthreads per K-tile, 2 CTAs/SM. 8 warps of 32x64.
// blockIdx.z = split-K slice (T tiles each). EPI: 0=none, 1=softplus.
#define STAGES 3
#define STG    32768u
#define GSMEM_TOTAL (STAGES * 32768)

template<int EPI>
__global__ __launch_bounds__(256, 2)
void gemm_mma(const __half* __restrict__ Ap, int lda,
              const __half* __restrict__ Bp, int ldb,
              float* __restrict__ C, int ldc, int T, long csplit)
{
    extern __shared__ __align__(1024) char smem[];
    const unsigned sb = smem_u32(smem);
    const int tid  = threadIdx.x;
    const int lane = tid & 31;
    const int wid  = tid >> 5;
    const int wm   = (wid & 3) * 32;   // warp row offset
    const int wn   = (wid >> 2) * 64;  // warp col offset
    const long bm  = (long)blockIdx.y * 128;
    const long bn  = (long)blockIdx.x * 128;

    Ap += (long)blockIdx.z * T * 64;
    Bp += (long)blockIdx.z * T * 64;
    C  += (long)blockIdx.z * csplit;

    const int ldr  = tid >> 3;
    const int ldc8 = (tid & 7) * 8;

    float acc[2][8][4];
#pragma unroll
    for (int i = 0; i < 2; i++)
#pragma unroll
        for (int j = 0; j < 8; j++)
#pragma unroll
            for (int r = 0; r < 4; r++) acc[i][j][r] = 0.0f;

    auto load_tile = [&](int t, int s) {
        const __half* Ab = Ap + bm * lda + (long)t * 64;
        const __half* Bb = Bp + bn * ldb + (long)t * 64;
        unsigned oa = sb + (unsigned)s * STG;
        unsigned ob = oa + 16384u;
#pragma unroll
        for (int i = 0; i < 4; i++) {
            int r = ldr + 32 * i;
            unsigned sw = SWZ128((unsigned)(r * 128 + ldc8 * 2));
            CP_ASYNC16(oa + sw, Ab + (long)r * lda + ldc8);
            CP_ASYNC16(ob + sw, Bb + (long)r * ldb + ldc8);
        }
        CP_COMMIT();
    };

#pragma unroll
    for (int s = 0; s < STAGES - 1; s++) {
        if (s < T) load_tile(s, s);
        else       CP_COMMIT();
    }

    const int lr = lane & 15;
    const int lh = (lane >> 4) * 16;

    int stage = 0;
    for (int t = 0; t < T; t++) {
        CP_WAIT(STAGES - 2);
        __syncthreads();
        {
            int tn = t + STAGES - 1;
            int sn = stage + STAGES - 1; if (sn >= STAGES) sn -= STAGES;
            if (tn < T) load_tile(tn, sn);
            else        CP_COMMIT();
        }
        const unsigned sA = sb + (unsigned)stage * STG;
        const unsigned sB = sA + 16384u;
#pragma unroll
        for (int ks = 0; ks < 4; ks++) {
            const int kb = ks * 32;
            unsigned af[2][4];
#pragma unroll
            for (int im = 0; im < 2; im++) {
                unsigned addr = sA + SWZ128((unsigned)((wm + im * 16 + lr) * 128 + kb + lh));
                ldsm4(af[im], addr);
            }
            unsigned bf[8][2];
#pragma unroll
            for (int jn = 0; jn < 4; jn++) {
                unsigned q[4];
                unsigned addr = sB + SWZ128((unsigned)((wn + jn * 16 + lr) * 128 + kb + lh));
                ldsm4(q, addr);
                bf[2 * jn][0]     = q[0];
                bf[2 * jn][1]     = q[2];
                bf[2 * jn + 1][0] = q[1];
                bf[2 * jn + 1][1] = q[3];
            }
#pragma unroll
            for (int im = 0; im < 2; im++)
#pragma unroll
                for (int j = 0; j < 8; j++)
                    mma16816(acc[im][j], af[im], bf[j]);
        }
        if (++stage == STAGES) stage = 0;
    }

    const int gid = lane >> 2;
    const int tig = lane & 3;
#pragma unroll
    for (int im = 0; im < 2; im++) {
        long m0 = bm + wm + im * 16 + gid;
#pragma unroll
        for (int j = 0; j < 8; j++) {
            long n0 = bn + wn + j * 8 + 2 * tig;
            float c0 = acc[im][j][0], c1 = acc[im][j][1];
            float c2 = acc[im][j][2], c3 = acc[im][j][3];
            if (EPI == 1) {
                c0 = softplusf(c0); c1 = softplusf(c1);
                c2 = softplusf(c2); c3 = softplusf(c3);
            }
            *reinterpret_cast<float2*>(C + m0 * ldc + n0)       = make_float2(c0, c1);
            *reinterpret_cast<float2*>(C + (m0 + 8) * ldc + n0) = make_float2(c2, c3);
        }
    }
}

// ---------------- depthwise causal conv(4) + bias + SiLU + u-split ---------
__global__ __launch_bounds__(256)
void conv_silu_kernel(const float* __restrict__ Wconv,
                      const float* __restrict__ bconv)
{
    long idx = (long)blockIdx.x * 256 + threadIdx.x;   // over B * L/4 * D
    int d  = (int)(idx & (D_INNER - 1));
    int t4 = (int)((idx >> 12) & (L_SEQ / 4 - 1));
    int b  = (int)(idx >> 20);
    int t0 = t4 * 4;

    float w0 = Wconv[d * 4 + 0], w1 = Wconv[d * 4 + 1];
    float w2 = Wconv[d * 4 + 2], w3 = Wconv[d * 4 + 3];
    float bc = bconv[d];

    const long rowbase = (long)(b * L_SEQ) * (2 * D_INNER) + d;
    float v[7];
#pragma unroll
    for (int i = 0; i < 7; i++) {
        int tt = t0 - 3 + i;
        v[i] = (tt >= 0) ? g_xz[rowbase + (long)tt * (2 * D_INNER)] : 0.0f;
    }

    long m = (long)(b * L_SEQ + t0);
#pragma unroll
    for (int q = 0; q < 4; q++) {
        float acc = bc;
        acc = fmaf(v[q],     w0, acc);
        acc = fmaf(v[q + 1], w1, acc);
        acc = fmaf(v[q + 2], w2, acc);
        acc = fmaf(v[q + 3], w3, acc);
        float uu = siluf(acc);
        g_u[(m + q) * D_INNER + d] = uu;
        split_store(g_ap, (m + q) * (2L * D_INNER) + d, D_INNER, uu);
    }
}

// ---------------- selective scan + epilogue + y-split ----------------------
__global__ __launch_bounds__(128)
void scan_kernel(const float* __restrict__ A_log,
                 const float* __restrict__ Dp)
{
    extern __shared__ __align__(16) float sBC[];   // [L_SEQ][32]
    const int b = blockIdx.x >> 5;
    const int d = ((blockIdx.x & 31) << 7) + threadIdx.x;
    const long base = (long)b * L_SEQ;

    for (int i = threadIdx.x * 4; i < L_SEQ * 32; i += 128 * 4) {
        int t = i >> 5, c = i & 31;
        *reinterpret_cast<float4*>(&sBC[i]) =
            *reinterpret_cast<const float4*>(&g_xdbl[(base + t) * XDBL_LD + DT_RANK + c]);
    }
    __syncthreads();

    float A[N_STATE];
#pragma unroll
    for (int n = 0; n < N_STATE; n++)
        A[n] = -__expf(A_log[d * N_STATE + n]);
    const float A1 = A[0];
    bool fast = true;
#pragma unroll
    for (int n = 1; n < N_STATE; n++)
        fast = fast && (fabsf(A[n] - (float)(n + 1) * A1) <= 1e-4f * fabsf(A[n]) + 1e-30f);

    const float Dd = Dp[d];
    float h[N_STATE];
#pragma unroll
    for (int n = 0; n < N_STATE; n++) h[n] = 0.0f;

    float pdt[4], pu[4], pr[4];
#pragma unroll
    for (int q = 0; q < 4; q++) {
        long row = base + q;
        pdt[q] = g_delta[row * D_INNER + d];
        pu[q]  = g_u[row * D_INNER + d];
        pr[q]  = g_xz[row * (2 * D_INNER) + D_INNER + d];
    }

    for (int t0 = 0; t0 < L_SEQ; t0 += 4) {
        float cdt[4], cu[4], cr[4];
#pragma unroll
        for (int q = 0; q < 4; q++) { cdt[q] = pdt[q]; cu[q] = pu[q]; cr[q] = pr[q]; }
        if (t0 + 4 < L_SEQ) {
#pragma unroll
            for (int q = 0; q < 4; q++) {
                long row = base + t0 + 4 + q;
                pdt[q] = g_delta[row * D_INNER + d];
                pu[q]  = g_u[row * D_INNER + d];
                pr[q]  = g_xz[row * (2 * D_INNER) + D_INNER + d];
            }
        }
#pragma unroll
        for (int q = 0; q < 4; q++) {
            const int t = t0 + q;
            const float* BC = &sBC[t * 32];
            const float dt = cdt[q], uu = cu[q], rr = cr[q];
            const float dtu = dt * uu;
            float yv = 0.0f;
            if (fast) {
                const float p = __expf(dt * A1);
                float da = p;
#pragma unroll
                for (int n = 0; n < N_STATE; n++) {
                    h[n] = fmaf(da, h[n], dtu * BC[n]);
                    yv = fmaf(h[n], BC[N_STATE + n], yv);
                    da *= p;
                }
            } else {
#pragma unroll
                for (int n = 0; n < N_STATE; n++) {
                    float da = __expf(dt * A[n]);
                    h[n] = fmaf(da, h[n], dtu * BC[n]);
                    yv = fmaf(h[n], BC[N_STATE + n], yv);
                }
            }
            float yo = (yv + uu * Dd) * siluf(rr);
            split_store(g_ap, (base + t) * (2L * D_INNER) + d, D_INNER, yo);
        }
    }
}

// ---------------- launcher ----------------
extern "C" void kernel_launch(void* const* d_in, const int* in_sizes, int n_in,
                              void* d_out, int out_size)
{
    (void)in_sizes; (void)n_in; (void)out_size;
    const float* x     = (const float*)d_in[0];
    const float* Win   = (const float*)d_in[1];
    const float* Wconv = (const float*)d_in[2];
    const float* bconv = (const float*)d_in[3];
    const float* Wx    = (const float*)d_in[4];
    const float* Wdt   = (const float*)d_in[5];
    const float* A_log = (const float*)d_in[6];
    const float* D     = (const float*)d_in[7];
    const float* Wout  = (const float*)d_in[8];
    float* out = (float*)d_out;

    float *xz, *xdbl, *delta, *partx, *party;
    __half *ap, *ap2, *wp;
    cudaGetSymbolAddress((void**)&xz,    g_xz);
    cudaGetSymbolAddress((void**)&xdbl,  g_xdbl);
    cudaGetSymbolAddress((void**)&delta, g_delta);
    cudaGetSymbolAddress((void**)&partx, g_partx);
    cudaGetSymbolAddress((void**)&party, g_party);
    cudaGetSymbolAddress((void**)&ap,    g_ap);
    cudaGetSymbolAddress((void**)&ap2,   g_ap2);
    cudaGetSymbolAddress((void**)&wp,    g_wp);

    cudaFuncSetAttribute(gemm_mma<0>, cudaFuncAttributeMaxDynamicSharedMemorySize, GSMEM_TOTAL);
    cudaFuncSetAttribute(gemm_mma<1>, cudaFuncAttributeMaxDynamicSharedMemorySize, GSMEM_TOTAL);
    const int scan_smem = L_SEQ * 32 * sizeof(float);
    cudaFuncSetAttribute(scan_kernel, cudaFuncAttributeMaxDynamicSharedMemorySize, scan_smem);

    // ---- GEMM1: xz = x @ Win   (2048 x 8192, K'=2048, T=32) ----
    prep_w<<<dim3(D_MODEL / 32, 2 * D_INNER / 32), 256>>>(Win, 2 * D_INNER, D_MODEL, wp);
    prep_act<<<(M_ROWS * D_MODEL) / 256, 256>>>(x, D_MODEL, D_MODEL, ap);
    gemm_mma<0><<<dim3(2 * D_INNER / 128, M_ROWS / 128, 1), 256, GSMEM_TOTAL>>>(
        ap, 2 * D_MODEL, wp, 2 * D_MODEL, xz, 2 * D_INNER, 32, 0);

    // ---- conv + SiLU -> u (fp32) + u' (split, into ap) ----
    conv_silu_kernel<<<(B_SZ * (L_SEQ / 4) * D_INNER) / 256, 256>>>(Wconv, bconv);

    // ---- x_dbl = u @ Wx   (2048 x 128pad, K'=8192; split-K x8, T=16) ----
    prep_w<<<dim3(D_INNER / 32, 96 / 32), 256>>>(Wx, 96, D_INNER, wp);
    zero_wp_pad<<<(32 * 8192) / 256, 256>>>(wp);
    gemm_mma<0><<<dim3(1, M_ROWS / 128, 8), 256, GSMEM_TOTAL>>>(
        ap, 2 * D_INNER, wp, 2 * D_INNER, partx, XDBL_LD, 16, (long)M_ROWS * XDBL_LD);
    reduce_parts<<<(M_ROWS * XDBL_LD) / 1024, 256>>>(partx, xdbl, (long)M_ROWS * XDBL_LD, 8);

    // ---- delta = softplus(x_dbl[:, :64] @ Wdt)  (2048 x 4096, K'=128, T=2) ----
    prep_w<<<dim3(DT_RANK / 32, D_INNER / 32), 256>>>(Wdt, D_INNER, DT_RANK, wp);
    prep_act<<<(M_ROWS * DT_RANK) / 256, 256>>>(xdbl, XDBL_LD, DT_RANK, ap2);
    gemm_mma<1><<<dim3(D_INNER / 128, M_ROWS / 128, 1), 256, GSMEM_TOTAL>>>(
        ap2, 2 * DT_RANK, wp, 2 * DT_RANK, delta, D_INNER, 2, 0);

    // ---- selective scan + epilogue -> y' (split, into ap) ----
    prep_w<<<dim3(D_INNER / 32, D_MODEL / 32), 256>>>(Wout, D_MODEL, D_INNER, wp);
    scan_kernel<<<64, 128, scan_smem>>>(A_log, D);

    // ---- out = y @ Wout   (2048 x 1024, K'=8192; split-K x4, T=32) ----
    gemm_mma<0><<<dim3(D_MODEL / 128, M_ROWS / 128, 4), 256, GSMEM_TOTAL>>>(
        ap, 2 * D_INNER, wp, 2 * D_INNER, party, D_MODEL, 32, (long)M_ROWS * D_MODEL);
    reduce_parts<<<(M_ROWS * D_MODEL) / 1024, 256>>>(party, out, (long)M_ROWS * D_MODEL, 4);
}

// round 14
// speedup vs baseline: 1.6263x; 1.2832x over previous
#include <cuda_runtime.h>
#include <cuda_fp16.h>

// ---------------- problem constants ----------------
#define B_SZ     2
#define L_SEQ    1024
#define D_MODEL  1024
#define D_INNER  4096
#define N_STATE  16
#define DT_RANK  64
#define M_ROWS   (B_SZ * L_SEQ)          // 2048
#define XDBL_LD  128                     // padded x_dbl leading dim

// ---------------- scratch (device globals; no allocs allowed) ----------------
__device__ float g_xz   [(long)M_ROWS * 2 * D_INNER]; // 2048 x 8192  (xc | res)
__device__ float g_u    [(long)M_ROWS * D_INNER];     // 2048 x 4096 (fp32 for scan)
__device__ float g_xdbl [(long)M_ROWS * XDBL_LD];     // 2048 x 128 (cols 96..127 pad)
__device__ float g_delta[(long)M_ROWS * D_INNER];     // 2048 x 4096
__device__ float g_partx[8L * M_ROWS * XDBL_LD];      // split-K partials (xdbl)
__device__ float g_party[4L * M_ROWS * D_MODEL];      // split-K partials (out)
__device__ __half g_ap [(long)M_ROWS * D_INNER];      // u'/y' fp16
__device__ __half g_ap2[(long)M_ROWS * DT_RANK];      // delta-GEMM A (fp16)
__device__ __half g_wp [(long)(2 * D_INNER) * D_MODEL]; // W' (fp16, transposed)

// ---------------- helpers ----------------
__device__ __forceinline__ float siluf(float x) { return x / (1.0f + __expf(-x)); }
__device__ __forceinline__ float softplusf(float x) {
    return (x > 0.0f) ? (x + log1pf(expf(-x))) : log1pf(expf(x));
}
__device__ __forceinline__ unsigned smem_u32(const void* p) {
    unsigned a;
    asm("{ .reg .u64 t; cvta.to.shared.u64 t, %1; cvt.u32.u64 %0, t; }" : "=r"(a) : "l"(p));
    return a;
}
#define SWZ128(o) ((o) ^ (((o) >> 3) & 0x70))

__device__ __forceinline__ void ldsm4(unsigned* r, unsigned addr) {
    asm volatile("ldmatrix.sync.aligned.m8n8.x4.shared.b16 {%0,%1,%2,%3}, [%4];"
                 : "=r"(r[0]), "=r"(r[1]), "=r"(r[2]), "=r"(r[3]) : "r"(addr));
}
__device__ __forceinline__ void mma16816(float* c, const unsigned* a, const unsigned* b) {
    asm volatile("mma.sync.aligned.m16n8k16.row.col.f32.f16.f16.f32 "
                 "{%0,%1,%2,%3}, {%4,%5,%6,%7}, {%8,%9}, {%0,%1,%2,%3};"
                 : "+f"(c[0]), "+f"(c[1]), "+f"(c[2]), "+f"(c[3])
                 : "r"(a[0]), "r"(a[1]), "r"(a[2]), "r"(a[3]), "r"(b[0]), "r"(b[1]));
}
#define CP_ASYNC16(dst, src) \
    asm volatile("cp.async.cg.shared.global [%0], [%1], 16;" :: "r"(dst), "l"(src) : "memory")
#define CP_COMMIT() asm volatile("cp.async.commit_group;" ::: "memory")
#define CP_WAIT(n)  asm volatile("cp.async.wait_group %0;" :: "n"(n) : "memory")

// ---------------- prep kernels (fp16 quantize) ----------------
__global__ __launch_bounds__(256)
void prep_act(const float* __restrict__ A, int lda, int K,
              __half* __restrict__ Ap)
{
    long idx = (long)blockIdx.x * 256 + threadIdx.x;
    long m = idx / K;
    int  k = (int)(idx % K);
    Ap[m * K + k] = __float2half_rn(A[m * lda + k]);
}

// W[K,N] -> W'[N,K] fp16 (transposed via smem tile)
__global__ __launch_bounds__(256)
void prep_w(const float* __restrict__ W, int N, int K,
            __half* __restrict__ Wp)
{
    __shared__ float th[32][33];
    int bk = blockIdx.x * 32, bn = blockIdx.y * 32;
    int tx = threadIdx.x & 31, ty = threadIdx.x >> 5;
#pragma unroll
    for (int j = 0; j < 4; j++) {
        int k = bk + ty + j * 8;
        th[ty + j * 8][tx] = W[(long)k * N + bn + tx];
    }
    __syncthreads();
#pragma unroll
    for (int j = 0; j < 4; j++) {
        int n = bn + ty + j * 8;
        Wp[(long)n * K + bk + tx] = __float2half_rn(th[tx][ty + j * 8]);
    }
}

// zero rows 96..127 of Wx' (N padded to 128, K=4096)
__global__ __launch_bounds__(256)
void zero_wp_pad(__half* __restrict__ Wp)
{
    long i = (long)blockIdx.x * 256 + threadIdx.x;
    Wp[96L * D_INNER + i] = __float2half_rn(0.0f);
}

__global__ __launch_bounds__(256)
void reduce_parts(const float* __restrict__ parts, float* __restrict__ dst,
                  long n, int np)
{
    long i = ((long)blockIdx.x * 256 + threadIdx.x) * 4;
    if (i >= n) return;
    float4 s = *reinterpret_cast<const float4*>(parts + i);
    for (int p = 1; p < np; p++) {
        float4 v = *reinterpret_cast<const float4*>(parts + (long)p * n + i);
        s.x += v.x; s.y += v.y; s.z += v.z; s.w += v.w;
    }
    *reinterpret_cast<float4*>(dst + i) = s;
}

// ---------------- warp-MMA fp16 GEMM: C[M,N] = A[M,K] @ W'[N,K]^T ----------
// BM=128, BN=128, BK=64 fp16 (128B rows, SW128), 3-stage cp.async ring,
// one __syncthreads per K-tile, 2 CTAs/SM. 8 warps of 32x64.
// blockIdx.z = split-K slice (T tiles each). EPI: 0=none, 1=softplus.
#define STAGES 3
#define STG    32768u
#define GSMEM_TOTAL (STAGES * 32768)

template<int EPI>
__global__ __launch_bounds__(256, 2)
void gemm_mma(const __half* __restrict__ Ap, int lda,
              const __half* __restrict__ Bp, int ldb,
              float* __restrict__ C, int ldc, int T, long csplit)
{
    extern __shared__ __align__(1024) char smem[];
    const unsigned sb = smem_u32(smem);
    const int tid  = threadIdx.x;
    const int lane = tid & 31;
    const int wid  = tid >> 5;
    const int wm   = (wid & 3) * 32;   // warp row offset
    const int wn   = (wid >> 2) * 64;  // warp col offset
    const long bm  = (long)blockIdx.y * 128;
    const long bn  = (long)blockIdx.x * 128;

    Ap += (long)blockIdx.z * T * 64;
    Bp += (long)blockIdx.z * T * 64;
    C  += (long)blockIdx.z * csplit;

    const int ldr  = tid >> 3;
    const int ldc8 = (tid & 7) * 8;

    float acc[2][8][4];
#pragma unroll
    for (int i = 0; i < 2; i++)
#pragma unroll
        for (int j = 0; j < 8; j++)
#pragma unroll
            for (int r = 0; r < 4; r++) acc[i][j][r] = 0.0f;

    auto load_tile = [&](int t, int s) {
        const __half* Ab = Ap + bm * lda + (long)t * 64;
        const __half* Bb = Bp + bn * ldb + (long)t * 64;
        unsigned oa = sb + (unsigned)s * STG;
        unsigned ob = oa + 16384u;
#pragma unroll
        for (int i = 0; i < 4; i++) {
            int r = ldr + 32 * i;
            unsigned sw = SWZ128((unsigned)(r * 128 + ldc8 * 2));
            CP_ASYNC16(oa + sw, Ab + (long)r * lda + ldc8);
            CP_ASYNC16(ob + sw, Bb + (long)r * ldb + ldc8);
        }
        CP_COMMIT();
    };

#pragma unroll
    for (int s = 0; s < STAGES - 1; s++) {
        if (s < T) load_tile(s, s);
        else       CP_COMMIT();
    }

    const int lr = lane & 15;
    const int lh = (lane >> 4) * 16;

    int stage = 0;
    for (int t = 0; t < T; t++) {
        CP_WAIT(STAGES - 2);
        __syncthreads();
        {
            int tn = t + STAGES - 1;
            int sn = stage + STAGES - 1; if (sn >= STAGES) sn -= STAGES;
            if (tn < T) load_tile(tn, sn);
            else        CP_COMMIT();
        }
        const unsigned sA = sb + (unsigned)stage * STG;
        const unsigned sB = sA + 16384u;
#pragma unroll
        for (int ks = 0; ks < 4; ks++) {
            const int kb = ks * 32;
            unsigned af[2][4];
#pragma unroll
            for (int im = 0; im < 2; im++) {
                unsigned addr = sA + SWZ128((unsigned)((wm + im * 16 + lr) * 128 + kb + lh));
                ldsm4(af[im], addr);
            }
            unsigned bf[8][2];
#pragma unroll
            for (int jn = 0; jn < 4; jn++) {
                unsigned q[4];
                unsigned addr = sB + SWZ128((unsigned)((wn + jn * 16 + lr) * 128 + kb + lh));
                ldsm4(q, addr);
                bf[2 * jn][0]     = q[0];
                bf[2 * jn][1]     = q[2];
                bf[2 * jn + 1][0] = q[1];
                bf[2 * jn + 1][1] = q[3];
            }
#pragma unroll
            for (int im = 0; im < 2; im++)
#pragma unroll
                for (int j = 0; j < 8; j++)
                    mma16816(acc[im][j], af[im], bf[j]);
        }
        if (++stage == STAGES) stage = 0;
    }

    const int gid = lane >> 2;
    const int tig = lane & 3;
#pragma unroll
    for (int im = 0; im < 2; im++) {
        long m0 = bm + wm + im * 16 + gid;
#pragma unroll
        for (int j = 0; j < 8; j++) {
            long n0 = bn + wn + j * 8 + 2 * tig;
            float c0 = acc[im][j][0], c1 = acc[im][j][1];
            float c2 = acc[im][j][2], c3 = acc[im][j][3];
            if (EPI == 1) {
                c0 = softplusf(c0); c1 = softplusf(c1);
                c2 = softplusf(c2); c3 = softplusf(c3);
            }
            *reinterpret_cast<float2*>(C + m0 * ldc + n0)       = make_float2(c0, c1);
            *reinterpret_cast<float2*>(C + (m0 + 8) * ldc + n0) = make_float2(c2, c3);
        }
    }
}

// ---------------- depthwise causal conv(4) + bias + SiLU + u-fp16 ----------
__global__ __launch_bounds__(256)
void conv_silu_kernel(const float* __restrict__ Wconv,
                      const float* __restrict__ bconv)
{
    long idx = (long)blockIdx.x * 256 + threadIdx.x;   // over B * L/4 * D
    int d  = (int)(idx & (D_INNER - 1));
    int t4 = (int)((idx >> 12) & (L_SEQ / 4 - 1));
    int b  = (int)(idx >> 20);
    int t0 = t4 * 4;

    float w0 = Wconv[d * 4 + 0], w1 = Wconv[d * 4 + 1];
    float w2 = Wconv[d * 4 + 2], w3 = Wconv[d * 4 + 3];
    float bc = bconv[d];

    const long rowbase = (long)(b * L_SEQ) * (2 * D_INNER) + d;
    float v[7];
#pragma unroll
    for (int i = 0; i < 7; i++) {
        int tt = t0 - 3 + i;
        v[i] = (tt >= 0) ? g_xz[rowbase + (long)tt * (2 * D_INNER)] : 0.0f;
    }

    long m = (long)(b * L_SEQ + t0);
#pragma unroll
    for (int q = 0; q < 4; q++) {
        float acc = bc;
        acc = fmaf(v[q],     w0, acc);
        acc = fmaf(v[q + 1], w1, acc);
        acc = fmaf(v[q + 2], w2, acc);
        acc = fmaf(v[q + 3], w3, acc);
        float uu = siluf(acc);
        g_u[(m + q) * D_INNER + d] = uu;
        g_ap[(m + q) * D_INNER + d] = __float2half_rn(uu);
    }
}

// ---------------- selective scan + epilogue + y-fp16 -----------------------
__global__ __launch_bounds__(128)
void scan_kernel(const float* __restrict__ A_log,
                 const float* __restrict__ Dp)
{
    extern __shared__ __align__(16) float sBC[];   // [L_SEQ][32]
    const int b = blockIdx.x >> 5;
    const int d = ((blockIdx.x & 31) << 7) + threadIdx.x;
    const long base = (long)b * L_SEQ;

    for (int i = threadIdx.x * 4; i < L_SEQ * 32; i += 128 * 4) {
        int t = i >> 5, c = i & 31;
        *reinterpret_cast<float4*>(&sBC[i]) =
            *reinterpret_cast<const float4*>(&g_xdbl[(base + t) * XDBL_LD + DT_RANK + c]);
    }
    __syncthreads();

    float A[N_STATE];
#pragma unroll
    for (int n = 0; n < N_STATE; n++)
        A[n] = -__expf(A_log[d * N_STATE + n]);
    const float A1 = A[0];
    bool fast = true;
#pragma unroll
    for (int n = 1; n < N_STATE; n++)
        fast = fast && (fabsf(A[n] - (float)(n + 1) * A1) <= 1e-4f * fabsf(A[n]) + 1e-30f);

    const float Dd = Dp[d];
    float h[N_STATE];
#pragma unroll
    for (int n = 0; n < N_STATE; n++) h[n] = 0.0f;

    float pdt[4], pu[4], pr[4];
#pragma unroll
    for (int q = 0; q < 4; q++) {
        long row = base + q;
        pdt[q] = g_delta[row * D_INNER + d];
        pu[q]  = g_u[row * D_INNER + d];
        pr[q]  = g_xz[row * (2 * D_INNER) + D_INNER + d];
    }

    for (int t0 = 0; t0 < L_SEQ; t0 += 4) {
        float cdt[4], cu[4], cr[4];
#pragma unroll
        for (int q = 0; q < 4; q++) { cdt[q] = pdt[q]; cu[q] = pu[q]; cr[q] = pr[q]; }
        if (t0 + 4 < L_SEQ) {
#pragma unroll
            for (int q = 0; q < 4; q++) {
                long row = base + t0 + 4 + q;
                pdt[q] = g_delta[row * D_INNER + d];
                pu[q]  = g_u[row * D_INNER + d];
                pr[q]  = g_xz[row * (2 * D_INNER) + D_INNER + d];
            }
        }
#pragma unroll
        for (int q = 0; q < 4; q++) {
            const int t = t0 + q;
            const float* BC = &sBC[t * 32];
            const float dt = cdt[q], uu = cu[q], rr = cr[q];
            const float dtu = dt * uu;
            float yv = 0.0f;
            if (fast) {
                const float p = __expf(dt * A1);
                float da = p;
#pragma unroll
                for (int n = 0; n < N_STATE; n++) {
                    h[n] = fmaf(da, h[n], dtu * BC[n]);
                    yv = fmaf(h[n], BC[N_STATE + n], yv);
                    da *= p;
                }
            } else {
#pragma unroll
                for (int n = 0; n < N_STATE; n++) {
                    float da = __expf(dt * A[n]);
                    h[n] = fmaf(da, h[n], dtu * BC[n]);
                    yv = fmaf(h[n], BC[N_STATE + n], yv);
                }
            }
            float yo = (yv + uu * Dd) * siluf(rr);
            g_ap[(base + t) * D_INNER + d] = __float2half_rn(yo);
        }
    }
}

// ---------------- launcher ----------------
extern "C" void kernel_launch(void* const* d_in, const int* in_sizes, int n_in,
                              void* d_out, int out_size)
{
    (void)in_sizes; (void)n_in; (void)out_size;
    const float* x     = (const float*)d_in[0];
    const float* Win   = (const float*)d_in[1];
    const float* Wconv = (const float*)d_in[2];
    const float* bconv = (const float*)d_in[3];
    const float* Wx    = (const float*)d_in[4];
    const float* Wdt   = (const float*)d_in[5];
    const float* A_log = (const float*)d_in[6];
    const float* D     = (const float*)d_in[7];
    const float* Wout  = (const float*)d_in[8];
    float* out = (float*)d_out;

    float *xz, *xdbl, *delta, *partx, *party;
    __half *ap, *ap2, *wp;
    cudaGetSymbolAddress((void**)&xz,    g_xz);
    cudaGetSymbolAddress((void**)&xdbl,  g_xdbl);
    cudaGetSymbolAddress((void**)&delta, g_delta);
    cudaGetSymbolAddress((void**)&partx, g_partx);
    cudaGetSymbolAddress((void**)&party, g_party);
    cudaGetSymbolAddress((void**)&ap,    g_ap);
    cudaGetSymbolAddress((void**)&ap2,   g_ap2);
    cudaGetSymbolAddress((void**)&wp,    g_wp);

    cudaFuncSetAttribute(gemm_mma<0>, cudaFuncAttributeMaxDynamicSharedMemorySize, GSMEM_TOTAL);
    cudaFuncSetAttribute(gemm_mma<1>, cudaFuncAttributeMaxDynamicSharedMemorySize, GSMEM_TOTAL);
    const int scan_smem = L_SEQ * 32 * sizeof(float);
    cudaFuncSetAttribute(scan_kernel, cudaFuncAttributeMaxDynamicSharedMemorySize, scan_smem);

    // ---- GEMM1: xz = x @ Win   (2048 x 8192, K=1024, T=16) ----
    prep_w<<<dim3(D_MODEL / 32, 2 * D_INNER / 32), 256>>>(Win, 2 * D_INNER, D_MODEL, wp);
    prep_act<<<(M_ROWS * D_MODEL) / 256, 256>>>(x, D_MODEL, D_MODEL, ap);
    gemm_mma<0><<<dim3(2 * D_INNER / 128, M_ROWS / 128, 1), 256, GSMEM_TOTAL>>>(
        ap, D_MODEL, wp, D_MODEL, xz, 2 * D_INNER, 16, 0);

    // ---- conv + SiLU -> u (fp32) + u (fp16, into ap) ----
    conv_silu_kernel<<<(B_SZ * (L_SEQ / 4) * D_INNER) / 256, 256>>>(Wconv, bconv);

    // ---- x_dbl = u @ Wx   (2048 x 128pad, K=4096; split-K x8, T=8) ----
    prep_w<<<dim3(D_INNER / 32, 96 / 32), 256>>>(Wx, 96, D_INNER, wp);
    zero_wp_pad<<<(32 * D_INNER) / 256, 256>>>(wp);
    gemm_mma<0><<<dim3(1, M_ROWS / 128, 8), 256, GSMEM_TOTAL>>>(
        ap, D_INNER, wp, D_INNER, partx, XDBL_LD, 8, (long)M_ROWS * XDBL_LD);
    reduce_parts<<<(M_ROWS * XDBL_LD) / 1024, 256>>>(partx, xdbl, (long)M_ROWS * XDBL_LD, 8);

    // ---- delta = softplus(x_dbl[:, :64] @ Wdt)  (2048 x 4096, K=64, T=1) ----
    prep_w<<<dim3(DT_RANK / 32, D_INNER / 32), 256>>>(Wdt, D_INNER, DT_RANK, wp);
    prep_act<<<(M_ROWS * DT_RANK) / 256, 256>>>(xdbl, XDBL_LD, DT_RANK, ap2);
    gemm_mma<1><<<dim3(D_INNER / 128, M_ROWS / 128, 1), 256, GSMEM_TOTAL>>>(
        ap2, DT_RANK, wp, DT_RANK, delta, D_INNER, 1, 0);

    // ---- selective scan + epilogue -> y (fp16, into ap) ----
    prep_w<<<dim3(D_INNER / 32, D_MODEL / 32), 256>>>(Wout, D_MODEL, D_INNER, wp);
    scan_kernel<<<64, 128, scan_smem>>>(A_log, D);

    // ---- out = y @ Wout   (2048 x 1024, K=4096; split-K x4, T=16) ----
    gemm_mma<0><<<dim3(D_MODEL / 128, M_ROWS / 128, 4), 256, GSMEM_TOTAL>>>(
        ap, D_INNER, wp, D_INNER, party, D_MODEL, 16, (long)M_ROWS * D_MODEL);
    reduce_parts<<<(M_ROWS * D_MODEL) / 1024, 256>>>(party, out, (long)M_ROWS * D_MODEL, 4);
}